// round 2
// baseline (speedup 1.0000x reference)
#include <cuda_runtime.h>
#include <cstddef>

// Problem constants
#define S_LEN 256
#define T_LEN 256
#define BSZ   32
#define DIN   2048
#define HID   1024
#define G4    4096   // 4*HID

// Scratch (device globals; allocation-free rule)
__device__ float g_xw[(size_t)S_LEN * BSZ * G4];     // per-layer input projection (128 MiB)
__device__ float g_out2[(size_t)S_LEN * BSZ * HID];  // 32 MiB
__device__ float g_out3[(size_t)S_LEN * BSZ * HID];  // 32 MiB
__device__ float g_h0[BSZ * HID];
__device__ float g_h1[BSZ * HID];
__device__ float g_c[BSZ * HID];

// ---------------------------------------------------------------------------
// Zero h (both buffers) and c at layer start
// ---------------------------------------------------------------------------
__global__ void zero_state_kernel() {
    int i = blockIdx.x * blockDim.x + threadIdx.x;
    if (i < BSZ * HID) {
        g_h0[i] = 0.f;
        g_h1[i] = 0.f;
        g_c[i]  = 0.f;
    }
}

// ---------------------------------------------------------------------------
// Header row: zeros except [0..3] = {513, 257, 258, 513}
// ---------------------------------------------------------------------------
__global__ void header_kernel(float* __restrict__ out) {
    int i = blockIdx.x * blockDim.x + threadIdx.x;
    if (i < BSZ * HID) {
        float v = 0.f;
        if (i == 0) v = (float)(1 + S_LEN + T_LEN);
        else if (i == 1) v = (float)(S_LEN + 1);
        else if (i == 2) v = (float)(S_LEN + 2);
        else if (i == 3) v = (float)(T_LEN + S_LEN + 1);
        out[i] = v;
    }
}

// ---------------------------------------------------------------------------
// src_tgt copy: out[(1+S+i)] = input[(1+S+i), :, :HID]
// ---------------------------------------------------------------------------
__global__ void copy_src_kernel(const float* __restrict__ in, float* __restrict__ out) {
    int l = blockIdx.x * blockDim.x + threadIdx.x;
    const int TOT = T_LEN * BSZ * (HID / 4);
    if (l < TOT) {
        int j4 = l % (HID / 4);
        int rb = l / (HID / 4);          // rb = i*BSZ + b
        int b  = rb % BSZ;
        int i  = rb / BSZ;
        size_t in_off  = ((size_t)(1 + S_LEN + i) * BSZ + b) * DIN + (size_t)j4 * 4;
        size_t out_off = ((size_t)(1 + S_LEN + i) * BSZ + b) * HID + (size_t)j4 * 4;
        float4 v = *(const float4*)(in + in_off);
        *(float4*)(out + out_off) = v;
    }
}

// ---------------------------------------------------------------------------
// SGEMM-NT with bias + optional elementwise input mask:
//   C[m,n] = sum_k (A[m,k]*mask[m,k]) * Bw[n,k] + bias1[n] + bias2[n]
// BM=BN=128, BK=16, 256 threads, 8x8 micro-tile.
// All dims assumed divisible (M=8192, N=4096, K in {1024,2048}).
// ---------------------------------------------------------------------------
__global__ void __launch_bounds__(256)
gemm_bias_kernel(const float* __restrict__ A, const float* __restrict__ Bw,
                 const float* __restrict__ bias1, const float* __restrict__ bias2,
                 const float* __restrict__ mask, float* __restrict__ C,
                 int M, int N, int K) {
    const int BM = 128, BN = 128, BK = 16;
    __shared__ float As[BK][BM];
    __shared__ float Bs[BK][BN];

    int tid = threadIdx.x;
    int bm = blockIdx.y * BM;
    int bn = blockIdx.x * BN;
    int tx = tid % 16;
    int ty = tid / 16;

    float acc[8][8];
#pragma unroll
    for (int i = 0; i < 8; i++)
#pragma unroll
        for (int j = 0; j < 8; j++) acc[i][j] = 0.f;

    int lr = tid / 4;          // 0..63
    int lc = (tid % 4) * 4;    // 0,4,8,12

    for (int k0 = 0; k0 < K; k0 += BK) {
        // Load A tile (with optional mask), store transposed
#pragma unroll
        for (int s = 0; s < 2; s++) {
            int r = lr + s * 64;
            size_t off = (size_t)(bm + r) * K + k0 + lc;
            float4 v = *(const float4*)(A + off);
            if (mask) {
                float4 mv = *(const float4*)(mask + off);
                v.x *= mv.x; v.y *= mv.y; v.z *= mv.z; v.w *= mv.w;
            }
            As[lc + 0][r] = v.x; As[lc + 1][r] = v.y;
            As[lc + 2][r] = v.z; As[lc + 3][r] = v.w;
        }
        // Load B tile (weights), store transposed
#pragma unroll
        for (int s = 0; s < 2; s++) {
            int r = lr + s * 64;
            size_t off = (size_t)(bn + r) * K + k0 + lc;
            float4 v = *(const float4*)(Bw + off);
            Bs[lc + 0][r] = v.x; Bs[lc + 1][r] = v.y;
            Bs[lc + 2][r] = v.z; Bs[lc + 3][r] = v.w;
        }
        __syncthreads();

#pragma unroll
        for (int kk = 0; kk < BK; kk++) {
            float rm[8], rn[8];
            *(float4*)&rm[0] = *(const float4*)&As[kk][ty * 8];
            *(float4*)&rm[4] = *(const float4*)&As[kk][ty * 8 + 4];
            *(float4*)&rn[0] = *(const float4*)&Bs[kk][tx * 8];
            *(float4*)&rn[4] = *(const float4*)&Bs[kk][tx * 8 + 4];
#pragma unroll
            for (int i = 0; i < 8; i++)
#pragma unroll
                for (int j = 0; j < 8; j++)
                    acc[i][j] += rm[i] * rn[j];
        }
        __syncthreads();
    }

    // Epilogue: add combined bias, store
#pragma unroll
    for (int i = 0; i < 8; i++) {
        int m = bm + ty * 8 + i;
#pragma unroll
        for (int j = 0; j < 8; j += 4) {
            int n = bn + tx * 8 + j;
            float4 o;
            o.x = acc[i][j + 0] + bias1[n + 0] + bias2[n + 0];
            o.y = acc[i][j + 1] + bias1[n + 1] + bias2[n + 1];
            o.z = acc[i][j + 2] + bias1[n + 2] + bias2[n + 2];
            o.w = acc[i][j + 3] + bias1[n + 3] + bias2[n + 3];
            *(float4*)(C + (size_t)m * N + n) = o;
        }
    }
}

// ---------------------------------------------------------------------------
// One LSTM timestep (fused recurrent GEMM + cell update + residual).
// Grid: 128 blocks; each block owns 8 hidden units (=> 32 gate rows) x 32 batches.
// h double-buffered across steps (cross-block read/write race otherwise).
// c owned per-unit (same block reads and writes) -> single buffer is safe.
// ---------------------------------------------------------------------------
__device__ __forceinline__ float sigmoidf_(float x) {
    return 1.0f / (1.0f + __expf(-x));
}

__global__ void __launch_bounds__(256)
lstm_step_kernel(const float* __restrict__ xw,    // (BSZ, 4H) slice for this t
                 const float* __restrict__ Whh,   // (4H, H)
                 const float* __restrict__ h_in,  // (BSZ, H)
                 float* __restrict__ h_out,       // (BSZ, H)
                 float* __restrict__ cst,         // (BSZ, H)
                 const float* __restrict__ res,   // (BSZ, H) or nullptr
                 float* __restrict__ out)         // (BSZ, H)
{
    const int UNITS = 8;    // hidden units per block
    const int ROWS = 32;    // 4 gates * 8 units
    const int BK = 64;

    __shared__ float Hs[BSZ][BK + 1];
    __shared__ float Ws[ROWS][BK + 1];
    __shared__ float Gs[ROWS][BSZ + 1];

    int tid = threadIdx.x;
    int jbase = blockIdx.x * UNITS;

    // micro-tile: 2 gate-rows x 2 batches per thread
    int c2   = (tid % 16) * 2;  // gate-row pair
    int bgrp = tid / 16;        // batch pair: bgrp, bgrp+16

    float acc00 = 0.f, acc01 = 0.f, acc10 = 0.f, acc11 = 0.f;

    for (int k0 = 0; k0 < HID; k0 += BK) {
        // Load h tile: 32 x 64
#pragma unroll
        for (int l = tid; l < BSZ * (BK / 4); l += 256) {
            int b = l / (BK / 4);
            int kk = (l % (BK / 4)) * 4;
            float4 v = *(const float4*)(h_in + (size_t)b * HID + k0 + kk);
            Hs[b][kk + 0] = v.x; Hs[b][kk + 1] = v.y;
            Hs[b][kk + 2] = v.z; Hs[b][kk + 3] = v.w;
        }
        // Load Whh tile: 32 gate rows x 64
#pragma unroll
        for (int l = tid; l < ROWS * (BK / 4); l += 256) {
            int r = l / (BK / 4);
            int kk = (l % (BK / 4)) * 4;
            int grow = (r / UNITS) * HID + jbase + (r % UNITS);
            float4 v = *(const float4*)(Whh + (size_t)grow * HID + k0 + kk);
            Ws[r][kk + 0] = v.x; Ws[r][kk + 1] = v.y;
            Ws[r][kk + 2] = v.z; Ws[r][kk + 3] = v.w;
        }
        __syncthreads();

#pragma unroll
        for (int kk = 0; kk < BK; kk++) {
            float w0 = Ws[c2][kk];
            float w1 = Ws[c2 + 1][kk];
            float ha = Hs[bgrp][kk];
            float hb = Hs[bgrp + 16][kk];
            acc00 += ha * w0; acc01 += ha * w1;
            acc10 += hb * w0; acc11 += hb * w1;
        }
        __syncthreads();
    }

    // Exchange gates through smem: Gs[gate_row][batch]
    Gs[c2][bgrp]          = acc00;
    Gs[c2 + 1][bgrp]      = acc01;
    Gs[c2][bgrp + 16]     = acc10;
    Gs[c2 + 1][bgrp + 16] = acc11;
    __syncthreads();

    // Cell update: one thread per (unit, batch)
    int u = tid % UNITS;
    int b = tid / UNITS;      // 0..31
    int j = jbase + u;
    size_t bi = (size_t)b * HID + j;

    float gi = Gs[0 * UNITS + u][b] + xw[(size_t)b * G4 + 0 * HID + j];
    float gf = Gs[1 * UNITS + u][b] + xw[(size_t)b * G4 + 1 * HID + j];
    float gg = Gs[2 * UNITS + u][b] + xw[(size_t)b * G4 + 2 * HID + j];
    float go = Gs[3 * UNITS + u][b] + xw[(size_t)b * G4 + 3 * HID + j];

    float ii = sigmoidf_(gi);
    float ff = sigmoidf_(gf);
    float oo = sigmoidf_(go);
    float gt = tanhf(gg);

    float cn = ff * cst[bi] + ii * gt;
    float hn = oo * tanhf(cn);

    cst[bi]   = cn;
    h_out[bi] = hn;
    out[bi]   = hn + (res ? res[bi] : 0.f);
}

// ---------------------------------------------------------------------------
// Host launcher
// ---------------------------------------------------------------------------
static void run_layer(const float* A, int K, const float* mask,
                      const float* Wih, const float* Whh,
                      const float* bih, const float* bhh,
                      const float* res_base, float* out_base, size_t out_stride,
                      float* xw, float* h0, float* h1, float* c) {
    // Input projection: M = S*B, N = 4H
    dim3 ggrid(G4 / 128, (S_LEN * BSZ) / 128);
    gemm_bias_kernel<<<ggrid, 256>>>(A, Wih, bih, bhh, mask, xw,
                                     S_LEN * BSZ, G4, K);
    zero_state_kernel<<<128, 256>>>();

    float* hin = h0;
    float* hout = h1;
    for (int t = 0; t < S_LEN; t++) {
        const float* res = res_base ? (res_base + (size_t)t * BSZ * HID) : nullptr;
        lstm_step_kernel<<<HID / 8, 256>>>(
            xw + (size_t)t * BSZ * G4, Whh, hin, hout, c, res,
            out_base + (size_t)t * out_stride);
        float* tmp = hin; hin = hout; hout = tmp;
    }
}

extern "C" void kernel_launch(void* const* d_in, const int* in_sizes, int n_in,
                              void* d_out, int out_size) {
    const float* input = (const float*)d_in[0];
    const float* Wih2 = (const float*)d_in[1];
    const float* Whh2 = (const float*)d_in[2];
    const float* bih2 = (const float*)d_in[3];
    const float* bhh2 = (const float*)d_in[4];
    const float* Wih3 = (const float*)d_in[5];
    const float* Whh3 = (const float*)d_in[6];
    const float* bih3 = (const float*)d_in[7];
    const float* bhh3 = (const float*)d_in[8];
    const float* Wih4 = (const float*)d_in[9];
    const float* Whh4 = (const float*)d_in[10];
    const float* bih4 = (const float*)d_in[11];
    const float* bhh4 = (const float*)d_in[12];
    const float* mask2 = (const float*)d_in[13];
    const float* mask3 = (const float*)d_in[14];
    float* out = (float*)d_out;

    // Device scratch pointers
    float *xw, *out2, *out3, *h0, *h1, *c;
    cudaGetSymbolAddress((void**)&xw, g_xw);
    cudaGetSymbolAddress((void**)&out2, g_out2);
    cudaGetSymbolAddress((void**)&out3, g_out3);
    cudaGetSymbolAddress((void**)&h0, g_h0);
    cudaGetSymbolAddress((void**)&h1, g_h1);
    cudaGetSymbolAddress((void**)&c, g_c);

    // Header + src_tgt passthrough
    header_kernel<<<(BSZ * HID + 255) / 256, 256>>>(out);
    copy_src_kernel<<<(T_LEN * BSZ * (HID / 4) + 255) / 256, 256>>>(input, out);

    // Layer 2: input rows [1, 1+S), K = DIN, no mask, no residual -> out2
    run_layer(input + (size_t)BSZ * DIN, DIN, nullptr,
              Wih2, Whh2, bih2, bhh2,
              nullptr, out2, (size_t)BSZ * HID,
              xw, h0, h1, c);

    // Layer 3: in = out2 (*mask2), residual out2 -> out3
    run_layer(out2, HID, mask2,
              Wih3, Whh3, bih3, bhh3,
              out2, out3, (size_t)BSZ * HID,
              xw, h0, h1, c);

    // Layer 4: in = out3 (*mask3), residual out3 -> d_out rows [1, 1+S)
    run_layer(out3, HID, mask3,
              Wih4, Whh4, bih4, bhh4,
              out3, out + (size_t)BSZ * HID, (size_t)BSZ * HID,
              xw, h0, h1, c);
}

// round 3
// speedup vs baseline: 2.0720x; 2.0720x over previous
#include <cuda_runtime.h>
#include <mma.h>
#include <cstddef>

using namespace nvcuda;

// Problem constants
#define S_LEN 256
#define T_LEN 256
#define BSZ   32
#define DIN   2048
#define HID   1024
#define G4    4096   // 4*HID

#define NBLK_REC 128   // persistent recurrence blocks (<= 148 SMs)

// Scratch (device globals; allocation-free rule)
__device__ float g_xw[(size_t)S_LEN * BSZ * G4];     // input projection (128 MiB)
__device__ float g_out2[(size_t)S_LEN * BSZ * HID];
__device__ float g_out3[(size_t)S_LEN * BSZ * HID];
__device__ float g_h0[BSZ * HID];
__device__ float g_h1[BSZ * HID];

// Grid barrier state
__device__ unsigned g_bar_count;
__device__ unsigned g_bar_gen;

__device__ __forceinline__ void grid_sync_() {
    __syncthreads();
    if (threadIdx.x == 0) {
        unsigned snap = atomicAdd(&g_bar_gen, 0u);
        __threadfence();
        unsigned arr = atomicAdd(&g_bar_count, 1u);
        if (arr == NBLK_REC - 1) {
            atomicExch(&g_bar_count, 0u);
            __threadfence();
            atomicAdd(&g_bar_gen, 1u);
        } else {
            while (atomicAdd(&g_bar_gen, 0u) == snap) { }
        }
    }
    __syncthreads();
}

// ---------------------------------------------------------------------------
// Header row
// ---------------------------------------------------------------------------
__global__ void header_kernel(float* __restrict__ out) {
    int i = blockIdx.x * blockDim.x + threadIdx.x;
    if (i < BSZ * HID) {
        float v = 0.f;
        if (i == 0) v = (float)(1 + S_LEN + T_LEN);
        else if (i == 1) v = (float)(S_LEN + 1);
        else if (i == 2) v = (float)(S_LEN + 2);
        else if (i == 3) v = (float)(T_LEN + S_LEN + 1);
        out[i] = v;
    }
}

// ---------------------------------------------------------------------------
// src_tgt copy
// ---------------------------------------------------------------------------
__global__ void copy_src_kernel(const float* __restrict__ in, float* __restrict__ out) {
    int l = blockIdx.x * blockDim.x + threadIdx.x;
    const int TOT = T_LEN * BSZ * (HID / 4);
    if (l < TOT) {
        int j4 = l % (HID / 4);
        int rb = l / (HID / 4);
        int b  = rb % BSZ;
        int i  = rb / BSZ;
        size_t in_off  = ((size_t)(1 + S_LEN + i) * BSZ + b) * DIN + (size_t)j4 * 4;
        size_t out_off = ((size_t)(1 + S_LEN + i) * BSZ + b) * HID + (size_t)j4 * 4;
        float4 v = *(const float4*)(in + in_off);
        *(float4*)(out + out_off) = v;
    }
}

// ---------------------------------------------------------------------------
// TF32 GEMM-NT (no bias): C[m,n] = sum_k (A[m,k]*mask[m,k]) * Bw[n,k]
// BM=BN=128, BK=32, 256 threads (8 warps = 4 Mwarps x 2 Nwarps).
// Warp tile 32x64 = 2x4 wmma m16n16k8.
// ---------------------------------------------------------------------------
#define ALD 40
__global__ void __launch_bounds__(256)
gemm_tf32_kernel(const float* __restrict__ A, const float* __restrict__ Bw,
                 const float* __restrict__ mask, float* __restrict__ C,
                 int M, int N, int K) {
    __shared__ float As[128 * ALD];
    __shared__ float Bs[128 * ALD];

    int tid = threadIdx.x;
    int bm = blockIdx.y * 128;
    int bn = blockIdx.x * 128;
    int warp = tid >> 5;
    int warpM = warp & 3;       // 0..3
    int warpN = warp >> 2;      // 0..1

    wmma::fragment<wmma::accumulator, 16, 16, 8, float> acc[2][4];
#pragma unroll
    for (int i = 0; i < 2; i++)
#pragma unroll
        for (int j = 0; j < 4; j++) wmma::fill_fragment(acc[i][j], 0.f);

    for (int k0 = 0; k0 < K; k0 += 32) {
#pragma unroll
        for (int v = 0; v < 4; v++) {
            int linear = v * 256 + tid;          // 0..1023
            int row = linear >> 3;               // 0..127
            int kq = (linear & 7) << 2;          // 0..28
            size_t aoff = (size_t)(bm + row) * K + k0 + kq;
            float4 va = *(const float4*)(A + aoff);
            if (mask) {
                float4 mv = *(const float4*)(mask + aoff);
                va.x *= mv.x; va.y *= mv.y; va.z *= mv.z; va.w *= mv.w;
            }
            *(float4*)&As[row * ALD + kq] = va;
            size_t boff = (size_t)(bn + row) * K + k0 + kq;
            float4 vb = *(const float4*)(Bw + boff);
            *(float4*)&Bs[row * ALD + kq] = vb;
        }
        __syncthreads();

#pragma unroll
        for (int kk = 0; kk < 32; kk += 8) {
            wmma::fragment<wmma::matrix_a, 16, 16, 8, wmma::precision::tf32, wmma::row_major> af[2];
            wmma::fragment<wmma::matrix_b, 16, 16, 8, wmma::precision::tf32, wmma::col_major> bf[4];
#pragma unroll
            for (int i = 0; i < 2; i++) {
                wmma::load_matrix_sync(af[i], &As[(warpM * 32 + i * 16) * ALD + kk], ALD);
#pragma unroll
                for (int e = 0; e < af[i].num_elements; e++)
                    af[i].x[e] = wmma::__float_to_tf32(af[i].x[e]);
            }
#pragma unroll
            for (int j = 0; j < 4; j++) {
                wmma::load_matrix_sync(bf[j], &Bs[(warpN * 64 + j * 16) * ALD + kk], ALD);
#pragma unroll
                for (int e = 0; e < bf[j].num_elements; e++)
                    bf[j].x[e] = wmma::__float_to_tf32(bf[j].x[e]);
            }
#pragma unroll
            for (int i = 0; i < 2; i++)
#pragma unroll
                for (int j = 0; j < 4; j++)
                    wmma::mma_sync(acc[i][j], af[i], bf[j], acc[i][j]);
        }
        __syncthreads();
    }

#pragma unroll
    for (int i = 0; i < 2; i++)
#pragma unroll
        for (int j = 0; j < 4; j++) {
            float* cp = C + (size_t)(bm + warpM * 32 + i * 16) * N + bn + warpN * 64 + j * 16;
            wmma::store_matrix_sync(cp, acc[i][j], N, wmma::mem_row_major);
        }
}

// ---------------------------------------------------------------------------
// Persistent LSTM layer: all 256 steps in one kernel.
// 128 blocks x 256 threads. Block owns 8 hidden units -> 32 gate rows.
// Whh slice (32x1024) resident in SMEM. c in registers. h double-buffered
// in global, grid barrier between steps.
// Warps: w&1 = Mtile(16 gate rows), (w>>1)&1 = Ntile(16 batches), w>>2 = K-half.
// ---------------------------------------------------------------------------
#define WLD 1032
#define HLD 72
#define GLD 36
#define REC_SMEM_FLOATS (32 * WLD + 2 * 32 * HLD + 2 * 32 * GLD)

__device__ __forceinline__ float sigmoidf_(float x) {
    return 1.0f / (1.0f + __expf(-x));
}

__global__ void __launch_bounds__(256, 1)
lstm_layer_kernel(const float* __restrict__ xw,    // (S,B,4H)
                  const float* __restrict__ Whh,   // (4H,H)
                  const float* __restrict__ bih,
                  const float* __restrict__ bhh,
                  const float* __restrict__ res,   // (S,B,H) or null
                  float* __restrict__ out,         // (S,B,H)
                  float* __restrict__ h0,
                  float* __restrict__ h1)
{
    extern __shared__ float sm[];
    float* Wsh = sm;                       // [32][WLD]
    float* Hs  = sm + 32 * WLD;            // [2][32][HLD]
    float* Gs  = Hs + 2 * 32 * HLD;        // [2][32][GLD]

    const int tid = threadIdx.x;
    const int jbase = blockIdx.x * 8;
    const int warp = tid >> 5;
    const int Mt = warp & 1;
    const int Nt = (warp >> 1) & 1;
    const int half = warp >> 2;

    // Load Whh slice into SMEM: local row r = g*8+u  ->  global row g*HID + jbase + u
    for (int idx = tid; idx < 32 * 256; idx += 256) {
        int r = idx >> 8;                  // 0..31
        int kq = (idx & 255) << 2;         // 0..1020
        int grow = (r >> 3) * HID + jbase + (r & 7);
        float4 v = *(const float4*)(Whh + (size_t)grow * HID + kq);
        *(float4*)&Wsh[r * WLD + kq] = v;
    }

    // Zero initial h (buffer h0, read at t=0)
    h0[blockIdx.x * 256 + tid] = 0.f;

    // Per-thread cell state + biases: thread (u = tid&7, b = tid>>3)
    const int u = tid & 7;
    const int bb = tid >> 3;
    const int j = jbase + u;
    float bias_[4];
#pragma unroll
    for (int g = 0; g < 4; g++)
        bias_[g] = bih[g * HID + j] + bhh[g * HID + j];
    float cc = 0.f;

    grid_sync_();

    for (int t = 0; t < S_LEN; t++) {
        const float* hin  = (t & 1) ? h1 : h0;
        float*       hout = (t & 1) ? h0 : h1;

        wmma::fragment<wmma::accumulator, 16, 16, 8, float> acc;
        wmma::fill_fragment(acc, 0.f);

#pragma unroll 1
        for (int it = 0; it < 8; it++) {
            // Stage both K-half chunks of h: Hs[hf][b][0..63] = h[b][hf*512 + it*64 + .]
#pragma unroll
            for (int v = 0; v < 4; v++) {
                int linear = v * 256 + tid;     // 0..1023
                int hf = linear >> 9;           // 0/1
                int rem = linear & 511;
                int b = rem >> 4;               // 0..31
                int kl = (rem & 15) << 2;       // 0..60
                float4 x = *(const float4*)(hin + (size_t)b * HID + hf * 512 + it * 64 + kl);
                *(float4*)&Hs[(hf * 32 + b) * HLD + kl] = x;
            }
            __syncthreads();

#pragma unroll
            for (int kk = 0; kk < 64; kk += 8) {
                wmma::fragment<wmma::matrix_a, 16, 16, 8, wmma::precision::tf32, wmma::row_major> af;
                wmma::fragment<wmma::matrix_b, 16, 16, 8, wmma::precision::tf32, wmma::col_major> bf;
                int kglob = half * 512 + it * 64 + kk;
                wmma::load_matrix_sync(af, &Wsh[(Mt * 16) * WLD + kglob], WLD);
                wmma::load_matrix_sync(bf, &Hs[(half * 32 + Nt * 16) * HLD + kk], HLD);
#pragma unroll
                for (int e = 0; e < af.num_elements; e++)
                    af.x[e] = wmma::__float_to_tf32(af.x[e]);
#pragma unroll
                for (int e = 0; e < bf.num_elements; e++)
                    bf.x[e] = wmma::__float_to_tf32(bf.x[e]);
                wmma::mma_sync(acc, af, bf, acc);
            }
            __syncthreads();
        }

        // Exchange gate partials through SMEM (two K-halves summed in epilogue)
        wmma::store_matrix_sync(&Gs[(half * 32 + Mt * 16) * GLD + Nt * 16], acc, GLD,
                                wmma::mem_row_major);
        __syncthreads();

        // Cell update
        const float* xwt = xw + ((size_t)t * BSZ + bb) * G4;
        float gi = Gs[(0 * 8 + u) * GLD + bb] + Gs[(32 + 0 * 8 + u) * GLD + bb]
                 + xwt[0 * HID + j] + bias_[0];
        float gf = Gs[(1 * 8 + u) * GLD + bb] + Gs[(32 + 1 * 8 + u) * GLD + bb]
                 + xwt[1 * HID + j] + bias_[1];
        float gg = Gs[(2 * 8 + u) * GLD + bb] + Gs[(32 + 2 * 8 + u) * GLD + bb]
                 + xwt[2 * HID + j] + bias_[2];
        float go = Gs[(3 * 8 + u) * GLD + bb] + Gs[(32 + 3 * 8 + u) * GLD + bb]
                 + xwt[3 * HID + j] + bias_[3];

        float ii = sigmoidf_(gi);
        float ff = sigmoidf_(gf);
        float oo = sigmoidf_(go);
        float gt = tanhf(gg);

        cc = ff * cc + ii * gt;
        float hn = oo * tanhf(cc);

        hout[(size_t)bb * HID + j] = hn;
        float ov = hn + (res ? res[((size_t)t * BSZ + bb) * HID + j] : 0.f);
        out[((size_t)t * BSZ + bb) * HID + j] = ov;

        grid_sync_();
    }
}

// ---------------------------------------------------------------------------
// Host launcher
// ---------------------------------------------------------------------------
static void run_layer(const float* A, int K, const float* mask,
                      const float* Wih, const float* Whh,
                      const float* bih, const float* bhh,
                      const float* res_base, float* out_base,
                      float* xw, float* h0, float* h1) {
    dim3 ggrid(G4 / 128, (S_LEN * BSZ) / 128);
    gemm_tf32_kernel<<<ggrid, 256>>>(A, Wih, mask, xw, S_LEN * BSZ, G4, K);

    size_t smem = REC_SMEM_FLOATS * sizeof(float);
    lstm_layer_kernel<<<NBLK_REC, 256, smem>>>(xw, Whh, bih, bhh,
                                               res_base, out_base, h0, h1);
}

extern "C" void kernel_launch(void* const* d_in, const int* in_sizes, int n_in,
                              void* d_out, int out_size) {
    const float* input = (const float*)d_in[0];
    const float* Wih2 = (const float*)d_in[1];
    const float* Whh2 = (const float*)d_in[2];
    const float* bih2 = (const float*)d_in[3];
    const float* bhh2 = (const float*)d_in[4];
    const float* Wih3 = (const float*)d_in[5];
    const float* Whh3 = (const float*)d_in[6];
    const float* bih3 = (const float*)d_in[7];
    const float* bhh3 = (const float*)d_in[8];
    const float* Wih4 = (const float*)d_in[9];
    const float* Whh4 = (const float*)d_in[10];
    const float* bih4 = (const float*)d_in[11];
    const float* bhh4 = (const float*)d_in[12];
    const float* mask2 = (const float*)d_in[13];
    const float* mask3 = (const float*)d_in[14];
    float* out = (float*)d_out;

    float *xw, *out2, *out3, *h0, *h1;
    cudaGetSymbolAddress((void**)&xw, g_xw);
    cudaGetSymbolAddress((void**)&out2, g_out2);
    cudaGetSymbolAddress((void**)&out3, g_out3);
    cudaGetSymbolAddress((void**)&h0, g_h0);
    cudaGetSymbolAddress((void**)&h1, g_h1);

    cudaFuncSetAttribute(lstm_layer_kernel,
                         cudaFuncAttributeMaxDynamicSharedMemorySize,
                         REC_SMEM_FLOATS * sizeof(float));

    header_kernel<<<(BSZ * HID + 255) / 256, 256>>>(out);
    copy_src_kernel<<<(T_LEN * BSZ * (HID / 4) + 255) / 256, 256>>>(input, out);

    // Layer 2
    run_layer(input + (size_t)BSZ * DIN, DIN, nullptr,
              Wih2, Whh2, bih2, bhh2,
              nullptr, out2, xw, h0, h1);

    // Layer 3 (input masked, residual out2)
    run_layer(out2, HID, mask2,
              Wih3, Whh3, bih3, bhh3,
              out2, out3, xw, h0, h1);

    // Layer 4 (input masked, residual out3) -> rows [1, 1+S) of output
    run_layer(out3, HID, mask3,
              Wih4, Whh4, bih4, bhh4,
              out3, out + (size_t)BSZ * HID, xw, h0, h1);
}

// round 4
// speedup vs baseline: 2.3876x; 1.1523x over previous
#include <cuda_runtime.h>
#include <mma.h>
#include <cstddef>

using namespace nvcuda;

// Problem constants
#define S_LEN 256
#define T_LEN 256
#define BSZ   32
#define DIN   2048
#define HID   1024
#define G4    4096   // 4*HID

#define NBLK_REC 128   // persistent recurrence blocks (<= 148 SMs)

// Scratch (device globals; allocation-free rule)
__device__ float g_xw[(size_t)S_LEN * BSZ * G4];      // input projection (128 MiB)
__device__ float g_out2[(size_t)S_LEN * BSZ * HID];
__device__ float g_out2m[(size_t)S_LEN * BSZ * HID];  // out2 * mask2
__device__ float g_out3[(size_t)S_LEN * BSZ * HID];
__device__ float g_out3m[(size_t)S_LEN * BSZ * HID];  // out3 * mask3
__device__ float g_h0[BSZ * HID];
__device__ float g_h1[BSZ * HID];

// Grid barrier state
__device__ unsigned g_bar_count;
__device__ unsigned g_bar_gen;

__device__ __forceinline__ float tf32r(float x) {
    float o;
    asm("cvt.rna.tf32.f32 %0, %1;" : "=f"(o) : "f"(x));
    return o;
}

// Grid barrier: arrive with one RED, poll with plain volatile loads (reads
// don't serialize in LTS the way atomic RMWs do).
__device__ __forceinline__ void grid_sync_() {
    __syncthreads();
    if (threadIdx.x == 0) {
        unsigned snap = *((volatile unsigned*)&g_bar_gen);
        __threadfence();
        unsigned old = atomicAdd(&g_bar_count, 1u);
        if (old == NBLK_REC - 1) {
            *((volatile unsigned*)&g_bar_count) = 0u;
            __threadfence();
            atomicAdd(&g_bar_gen, 1u);
        } else {
            while (*((volatile unsigned*)&g_bar_gen) == snap) { }
        }
        __threadfence();
    }
    __syncthreads();
}

// ---------------------------------------------------------------------------
// Header row
// ---------------------------------------------------------------------------
__global__ void header_kernel(float* __restrict__ out) {
    int i = blockIdx.x * blockDim.x + threadIdx.x;
    if (i < BSZ * HID) {
        float v = 0.f;
        if (i == 0) v = (float)(1 + S_LEN + T_LEN);
        else if (i == 1) v = (float)(S_LEN + 1);
        else if (i == 2) v = (float)(S_LEN + 2);
        else if (i == 3) v = (float)(T_LEN + S_LEN + 1);
        out[i] = v;
    }
}

// ---------------------------------------------------------------------------
// src_tgt copy
// ---------------------------------------------------------------------------
__global__ void copy_src_kernel(const float* __restrict__ in, float* __restrict__ out) {
    int l = blockIdx.x * blockDim.x + threadIdx.x;
    const int TOT = T_LEN * BSZ * (HID / 4);
    if (l < TOT) {
        int j4 = l % (HID / 4);
        int rb = l / (HID / 4);
        int b  = rb % BSZ;
        int i  = rb / BSZ;
        size_t in_off  = ((size_t)(1 + S_LEN + i) * BSZ + b) * DIN + (size_t)j4 * 4;
        size_t out_off = ((size_t)(1 + S_LEN + i) * BSZ + b) * HID + (size_t)j4 * 4;
        float4 v = *(const float4*)(in + in_off);
        *(float4*)(out + out_off) = v;
    }
}

// ---------------------------------------------------------------------------
// TF32 GEMM-NT: C[m,n] = sum_k A[m,k] * Bw[n,k]
// BM=BN=128, BK=32, 256 threads (8 warps = 4 Mwarps x 2 Nwarps).
// Register-prefetch pipeline; tf32 rounding applied at smem store (no
// per-fragment conversion in the mma loop).
// ---------------------------------------------------------------------------
#define ALD 40
__global__ void __launch_bounds__(256)
gemm_tf32_kernel(const float* __restrict__ A, const float* __restrict__ Bw,
                 float* __restrict__ C, int M, int N, int K) {
    __shared__ float As[128 * ALD];
    __shared__ float Bs[128 * ALD];

    int tid = threadIdx.x;
    int bm = blockIdx.y * 128;
    int bn = blockIdx.x * 128;
    int warp = tid >> 5;
    int warpM = warp & 3;       // 0..3
    int warpN = warp >> 2;      // 0..1

    wmma::fragment<wmma::accumulator, 16, 16, 8, float> acc[2][4];
#pragma unroll
    for (int i = 0; i < 2; i++)
#pragma unroll
        for (int j = 0; j < 4; j++) wmma::fill_fragment(acc[i][j], 0.f);

    float4 ra[4], rb[4];
#pragma unroll
    for (int v = 0; v < 4; v++) {
        int linear = v * 256 + tid;
        int row = linear >> 3;
        int kq = (linear & 7) << 2;
        ra[v] = *(const float4*)(A + (size_t)(bm + row) * K + kq);
        rb[v] = *(const float4*)(Bw + (size_t)(bn + row) * K + kq);
    }

    for (int k0 = 0; k0 < K; k0 += 32) {
        // Store prefetched tile to smem with tf32 rounding
#pragma unroll
        for (int v = 0; v < 4; v++) {
            int linear = v * 256 + tid;
            int row = linear >> 3;
            int kq = (linear & 7) << 2;
            float4 a = ra[v];
            a.x = tf32r(a.x); a.y = tf32r(a.y); a.z = tf32r(a.z); a.w = tf32r(a.w);
            *(float4*)&As[row * ALD + kq] = a;
            float4 b = rb[v];
            b.x = tf32r(b.x); b.y = tf32r(b.y); b.z = tf32r(b.z); b.w = tf32r(b.w);
            *(float4*)&Bs[row * ALD + kq] = b;
        }
        __syncthreads();

        // Prefetch next tile (overlaps with mma below)
        if (k0 + 32 < K) {
#pragma unroll
            for (int v = 0; v < 4; v++) {
                int linear = v * 256 + tid;
                int row = linear >> 3;
                int kq = (linear & 7) << 2;
                ra[v] = *(const float4*)(A + (size_t)(bm + row) * K + k0 + 32 + kq);
                rb[v] = *(const float4*)(Bw + (size_t)(bn + row) * K + k0 + 32 + kq);
            }
        }

#pragma unroll
        for (int kk = 0; kk < 32; kk += 8) {
            wmma::fragment<wmma::matrix_a, 16, 16, 8, wmma::precision::tf32, wmma::row_major> af[2];
            wmma::fragment<wmma::matrix_b, 16, 16, 8, wmma::precision::tf32, wmma::col_major> bf[4];
#pragma unroll
            for (int i = 0; i < 2; i++)
                wmma::load_matrix_sync(af[i], &As[(warpM * 32 + i * 16) * ALD + kk], ALD);
#pragma unroll
            for (int j = 0; j < 4; j++)
                wmma::load_matrix_sync(bf[j], &Bs[(warpN * 64 + j * 16) * ALD + kk], ALD);
#pragma unroll
            for (int i = 0; i < 2; i++)
#pragma unroll
                for (int j = 0; j < 4; j++)
                    wmma::mma_sync(acc[i][j], af[i], bf[j], acc[i][j]);
        }
        __syncthreads();
    }

#pragma unroll
    for (int i = 0; i < 2; i++)
#pragma unroll
        for (int j = 0; j < 4; j++) {
            float* cp = C + (size_t)(bm + warpM * 32 + i * 16) * N + bn + warpN * 64 + j * 16;
            wmma::store_matrix_sync(cp, acc[i][j], N, wmma::mem_row_major);
        }
}

// ---------------------------------------------------------------------------
// Persistent LSTM layer. 128 blocks x 256 threads; block owns 8 hidden units
// (32 gate rows). Whh slice tf32-rounded and resident in SMEM. h double-
// buffered in global; Hs staged in 4 chunks of 128k with double buffering and
// register prefetch. 2 accumulators halve the mma dependency chain. xw/res/
// mask for step t+1 prefetched into registers during step t.
// Also writes out*mask into outm (feeds the next layer's projection GEMM).
// ---------------------------------------------------------------------------
#define WLD 1032
#define HLD 136
#define GLD 36
#define HS_BUF (2 * 32 * HLD)            // one Hs buffer: 2 halves x 32 batches
#define REC_SMEM_FLOATS (32 * WLD + 2 * HS_BUF + 2 * 32 * GLD)

__device__ __forceinline__ float sigmoidf_(float x) {
    return 1.0f / (1.0f + __expf(-x));
}

__global__ void __launch_bounds__(256, 1)
lstm_layer_kernel(const float* __restrict__ xw,     // (S,B,4H)
                  const float* __restrict__ Whh,    // (4H,H)
                  const float* __restrict__ bih,
                  const float* __restrict__ bhh,
                  const float* __restrict__ res,    // (S,B,H) or null
                  const float* __restrict__ maskp,  // (S,B,H) or null
                  float* __restrict__ out,          // (S,B,H)
                  float* __restrict__ outm,         // (S,B,H) or null
                  float* __restrict__ h0,
                  float* __restrict__ h1)
{
    extern __shared__ float sm[];
    float* Wsh = sm;                        // [32][WLD]
    float* Hs  = sm + 32 * WLD;             // [2][2*32][HLD]
    float* Gs  = Hs + 2 * HS_BUF;           // [2][32][GLD]

    const int tid = threadIdx.x;
    const int jbase = blockIdx.x * 8;
    const int warp = tid >> 5;
    const int Mt = warp & 1;
    const int Nt = (warp >> 1) & 1;
    const int half = warp >> 2;

    // Load Whh slice, tf32-rounded: local row r = g*8+u -> global g*HID+jbase+u
    for (int idx = tid; idx < 32 * 256; idx += 256) {
        int r = idx >> 8;
        int kq = (idx & 255) << 2;
        int grow = (r >> 3) * HID + jbase + (r & 7);
        float4 v = *(const float4*)(Whh + (size_t)grow * HID + kq);
        v.x = tf32r(v.x); v.y = tf32r(v.y); v.z = tf32r(v.z); v.w = tf32r(v.w);
        *(float4*)&Wsh[r * WLD + kq] = v;
    }

    // Zero initial h (buffer h0, read at t=0)
    h0[blockIdx.x * 256 + tid] = 0.f;

    const int u = tid & 7;
    const int bb = tid >> 3;
    const int j = jbase + u;
    float bias_[4];
#pragma unroll
    for (int g = 0; g < 4; g++)
        bias_[g] = bih[g * HID + j] + bhh[g * HID + j];
    float cc = 0.f;

    // Prefetch step-0 xw / res / mask
    float xwc[4], resc = 0.f, maskc = 1.f;
    {
        const float* xwt = xw + (size_t)bb * G4;
#pragma unroll
        for (int g = 0; g < 4; g++) xwc[g] = xwt[g * HID + j];
        if (res)   resc  = res[(size_t)bb * HID + j];
        if (maskp) maskc = maskp[(size_t)bb * HID + j];
    }

    grid_sync_();

    for (int t = 0; t < S_LEN; t++) {
        const float* hin  = (t & 1) ? h1 : h0;
        float*       hout = (t & 1) ? h0 : h1;

        // Stage chunk 0 into Hs buffer 0 (tf32-rounded)
#pragma unroll
        for (int v = 0; v < 8; v++) {
            int linear = v * 256 + tid;          // 0..2047
            int hf = linear >> 10;
            int rem = linear & 1023;
            int b = rem >> 5;
            int kl = (rem & 31) << 2;
            float4 x = *(const float4*)(hin + (size_t)b * HID + hf * 512 + kl);
            x.x = tf32r(x.x); x.y = tf32r(x.y); x.z = tf32r(x.z); x.w = tf32r(x.w);
            *(float4*)&Hs[(hf * 32 + b) * HLD + kl] = x;
        }

        // Prefetch next step's xw / res / mask (independent of h)
        float xwn[4] = {0.f, 0.f, 0.f, 0.f};
        float resn = 0.f, maskn = 1.f;
        if (t + 1 < S_LEN) {
            const float* xwt = xw + ((size_t)(t + 1) * BSZ + bb) * G4;
#pragma unroll
            for (int g = 0; g < 4; g++) xwn[g] = xwt[g * HID + j];
            if (res)   resn  = res[((size_t)(t + 1) * BSZ + bb) * HID + j];
            if (maskp) maskn = maskp[((size_t)(t + 1) * BSZ + bb) * HID + j];
        }
        __syncthreads();

        wmma::fragment<wmma::accumulator, 16, 16, 8, float> a0, a1;
        wmma::fill_fragment(a0, 0.f);
        wmma::fill_fragment(a1, 0.f);

#pragma unroll
        for (int it = 0; it < 4; it++) {
            // Prefetch chunk it+1 into registers (overlaps mma)
            float4 pre[8];
            if (it < 3) {
#pragma unroll
                for (int v = 0; v < 8; v++) {
                    int linear = v * 256 + tid;
                    int hf = linear >> 10;
                    int rem = linear & 1023;
                    int b = rem >> 5;
                    int kl = (rem & 31) << 2;
                    pre[v] = *(const float4*)(hin + (size_t)b * HID + hf * 512 +
                                              (it + 1) * 128 + kl);
                }
            }

            const float* Hb = Hs + (it & 1) * HS_BUF;
#pragma unroll
            for (int kk = 0; kk < 128; kk += 16) {
                wmma::fragment<wmma::matrix_a, 16, 16, 8, wmma::precision::tf32, wmma::row_major> af0, af1;
                wmma::fragment<wmma::matrix_b, 16, 16, 8, wmma::precision::tf32, wmma::col_major> bf0, bf1;
                int kglob = half * 512 + it * 128 + kk;
                wmma::load_matrix_sync(af0, &Wsh[(Mt * 16) * WLD + kglob], WLD);
                wmma::load_matrix_sync(bf0, &Hb[(half * 32 + Nt * 16) * HLD + kk], HLD);
                wmma::load_matrix_sync(af1, &Wsh[(Mt * 16) * WLD + kglob + 8], WLD);
                wmma::load_matrix_sync(bf1, &Hb[(half * 32 + Nt * 16) * HLD + kk + 8], HLD);
                wmma::mma_sync(a0, af0, bf0, a0);
                wmma::mma_sync(a1, af1, bf1, a1);
            }

            if (it < 3) {
                __syncthreads();   // all warps done reading buffer (it+1)&1 from it-1
                float* Hn = Hs + ((it + 1) & 1) * HS_BUF;
#pragma unroll
                for (int v = 0; v < 8; v++) {
                    int linear = v * 256 + tid;
                    int hf = linear >> 10;
                    int rem = linear & 1023;
                    int b = rem >> 5;
                    int kl = (rem & 31) << 2;
                    float4 x = pre[v];
                    x.x = tf32r(x.x); x.y = tf32r(x.y); x.z = tf32r(x.z); x.w = tf32r(x.w);
                    *(float4*)&Hn[(hf * 32 + b) * HLD + kl] = x;
                }
                __syncthreads();   // staged data visible before next it's mma
            }
        }

        // Combine the two accumulators
#pragma unroll
        for (int e = 0; e < a0.num_elements; e++) a0.x[e] += a1.x[e];

        // Exchange gate partials through SMEM (two K-halves summed in epilogue)
        wmma::store_matrix_sync(&Gs[(half * 32 + Mt * 16) * GLD + Nt * 16], a0, GLD,
                                wmma::mem_row_major);
        __syncthreads();

        // Cell update (uses prefetched xwc / resc / maskc)
        float gi = Gs[(0 * 8 + u) * GLD + bb] + Gs[(32 + 0 * 8 + u) * GLD + bb] + xwc[0] + bias_[0];
        float gf = Gs[(1 * 8 + u) * GLD + bb] + Gs[(32 + 1 * 8 + u) * GLD + bb] + xwc[1] + bias_[1];
        float gg = Gs[(2 * 8 + u) * GLD + bb] + Gs[(32 + 2 * 8 + u) * GLD + bb] + xwc[2] + bias_[2];
        float go = Gs[(3 * 8 + u) * GLD + bb] + Gs[(32 + 3 * 8 + u) * GLD + bb] + xwc[3] + bias_[3];

        float ii = sigmoidf_(gi);
        float ff = sigmoidf_(gf);
        float oo = sigmoidf_(go);
        float gt = tanhf(gg);

        cc = ff * cc + ii * gt;
        float hn = oo * tanhf(cc);

        hout[(size_t)bb * HID + j] = hn;
        float ov = hn + resc;
        size_t ooff = ((size_t)t * BSZ + bb) * HID + j;
        out[ooff] = ov;
        if (outm) outm[ooff] = ov * maskc;

#pragma unroll
        for (int g = 0; g < 4; g++) xwc[g] = xwn[g];
        resc = resn;
        maskc = maskn;

        grid_sync_();
    }
}

// ---------------------------------------------------------------------------
// Host launcher
// ---------------------------------------------------------------------------
static void run_layer(const float* A, int K,
                      const float* Wih, const float* Whh,
                      const float* bih, const float* bhh,
                      const float* res_base, const float* maskp,
                      float* out_base, float* outm,
                      float* xw, float* h0, float* h1) {
    dim3 ggrid(G4 / 128, (S_LEN * BSZ) / 128);
    gemm_tf32_kernel<<<ggrid, 256>>>(A, Wih, xw, S_LEN * BSZ, G4, K);

    size_t smem = REC_SMEM_FLOATS * sizeof(float);
    lstm_layer_kernel<<<NBLK_REC, 256, smem>>>(xw, Whh, bih, bhh,
                                               res_base, maskp, out_base, outm,
                                               h0, h1);
}

extern "C" void kernel_launch(void* const* d_in, const int* in_sizes, int n_in,
                              void* d_out, int out_size) {
    const float* input = (const float*)d_in[0];
    const float* Wih2 = (const float*)d_in[1];
    const float* Whh2 = (const float*)d_in[2];
    const float* bih2 = (const float*)d_in[3];
    const float* bhh2 = (const float*)d_in[4];
    const float* Wih3 = (const float*)d_in[5];
    const float* Whh3 = (const float*)d_in[6];
    const float* bih3 = (const float*)d_in[7];
    const float* bhh3 = (const float*)d_in[8];
    const float* Wih4 = (const float*)d_in[9];
    const float* Whh4 = (const float*)d_in[10];
    const float* bih4 = (const float*)d_in[11];
    const float* bhh4 = (const float*)d_in[12];
    const float* mask2 = (const float*)d_in[13];
    const float* mask3 = (const float*)d_in[14];
    float* out = (float*)d_out;

    float *xw, *out2, *out2m, *out3, *out3m, *h0, *h1;
    cudaGetSymbolAddress((void**)&xw, g_xw);
    cudaGetSymbolAddress((void**)&out2, g_out2);
    cudaGetSymbolAddress((void**)&out2m, g_out2m);
    cudaGetSymbolAddress((void**)&out3, g_out3);
    cudaGetSymbolAddress((void**)&out3m, g_out3m);
    cudaGetSymbolAddress((void**)&h0, g_h0);
    cudaGetSymbolAddress((void**)&h1, g_h1);

    cudaFuncSetAttribute(lstm_layer_kernel,
                         cudaFuncAttributeMaxDynamicSharedMemorySize,
                         REC_SMEM_FLOATS * sizeof(float));

    header_kernel<<<(BSZ * HID + 255) / 256, 256>>>(out);
    copy_src_kernel<<<(T_LEN * BSZ * (HID / 4) + 255) / 256, 256>>>(input, out);

    // Layer 2: input slice, K=DIN; no residual; writes out2 and out2*mask2
    run_layer(input + (size_t)BSZ * DIN, DIN,
              Wih2, Whh2, bih2, bhh2,
              nullptr, mask2, out2, out2m,
              xw, h0, h1);

    // Layer 3: in = out2m; residual out2; writes out3 and out3*mask3
    run_layer(out2m, HID,
              Wih3, Whh3, bih3, bhh3,
              out2, mask3, out3, out3m,
              xw, h0, h1);

    // Layer 4: in = out3m; residual out3 -> rows [1, 1+S) of output
    run_layer(out3m, HID,
              Wih4, Whh4, bih4, bhh4,
              out3, nullptr, out + (size_t)BSZ * HID, nullptr,
              xw, h0, h1);
}

// round 5
// speedup vs baseline: 5.3949x; 2.2595x over previous
#include <cuda_runtime.h>
#include <cuda_fp16.h>
#include <mma.h>
#include <cstddef>

using namespace nvcuda;

// Problem constants
#define S_LEN 256
#define T_LEN 256
#define BSZ   32
#define DIN   2048
#define HID   1024
#define G4    4096   // 4*HID

#define NBLK_REC 64   // persistent recurrence blocks

// Scratch (device globals; allocation-free rule)
__device__ float g_xw[(size_t)S_LEN * BSZ * G4];      // input projection (128 MiB)
__device__ float g_out2[(size_t)S_LEN * BSZ * HID];
__device__ float g_out2m[(size_t)S_LEN * BSZ * HID];  // out2 * mask2
__device__ float g_out3[(size_t)S_LEN * BSZ * HID];
__device__ float g_out3m[(size_t)S_LEN * BSZ * HID];  // out3 * mask3
__device__ __half g_h0[BSZ * HID];
__device__ __half g_h1[BSZ * HID];

// Grid barrier state
__device__ unsigned g_bar_count;
__device__ unsigned g_bar_gen;

// Grid barrier: arrive with atomicAdd, poll with volatile loads.
__device__ __forceinline__ void grid_sync_() {
    __syncthreads();
    if (threadIdx.x == 0) {
        unsigned snap = *((volatile unsigned*)&g_bar_gen);
        __threadfence();
        unsigned old = atomicAdd(&g_bar_count, 1u);
        if (old == NBLK_REC - 1) {
            *((volatile unsigned*)&g_bar_count) = 0u;
            __threadfence();
            atomicAdd(&g_bar_gen, 1u);
        } else {
            while (*((volatile unsigned*)&g_bar_gen) == snap) { }
        }
        __threadfence();
    }
    __syncthreads();
}

// ---------------------------------------------------------------------------
// Header row
// ---------------------------------------------------------------------------
__global__ void header_kernel(float* __restrict__ out) {
    int i = blockIdx.x * blockDim.x + threadIdx.x;
    if (i < BSZ * HID) {
        float v = 0.f;
        if (i == 0) v = (float)(1 + S_LEN + T_LEN);
        else if (i == 1) v = (float)(S_LEN + 1);
        else if (i == 2) v = (float)(S_LEN + 2);
        else if (i == 3) v = (float)(T_LEN + S_LEN + 1);
        out[i] = v;
    }
}

// ---------------------------------------------------------------------------
// src_tgt copy
// ---------------------------------------------------------------------------
__global__ void copy_src_kernel(const float* __restrict__ in, float* __restrict__ out) {
    int l = blockIdx.x * blockDim.x + threadIdx.x;
    const int TOT = T_LEN * BSZ * (HID / 4);
    if (l < TOT) {
        int j4 = l % (HID / 4);
        int rb = l / (HID / 4);
        int b  = rb % BSZ;
        int i  = rb / BSZ;
        size_t in_off  = ((size_t)(1 + S_LEN + i) * BSZ + b) * DIN + (size_t)j4 * 4;
        size_t out_off = ((size_t)(1 + S_LEN + i) * BSZ + b) * HID + (size_t)j4 * 4;
        float4 v = *(const float4*)(in + in_off);
        *(float4*)(out + out_off) = v;
    }
}

// ---------------------------------------------------------------------------
// FP16 GEMM-NT (fp32 accumulate): C[m,n] = sum_k A[m,k] * Bw[n,k]
// BM=BN=128, BK=32, 256 threads (8 warps = 4 Mwarps x 2 Nwarps).
// Register-prefetch pipeline; fp32->fp16 conversion at smem store.
// ---------------------------------------------------------------------------
#define ALD 40  // halves
__global__ void __launch_bounds__(256)
gemm_fp16_kernel(const float* __restrict__ A, const float* __restrict__ Bw,
                 float* __restrict__ C, int M, int N, int K) {
    __shared__ __half As[128 * ALD];
    __shared__ __half Bs[128 * ALD];

    int tid = threadIdx.x;
    int bm = blockIdx.y * 128;
    int bn = blockIdx.x * 128;
    int warp = tid >> 5;
    int warpM = warp & 3;       // 0..3
    int warpN = warp >> 2;      // 0..1

    wmma::fragment<wmma::accumulator, 16, 16, 16, float> acc[2][4];
#pragma unroll
    for (int i = 0; i < 2; i++)
#pragma unroll
        for (int j = 0; j < 4; j++) wmma::fill_fragment(acc[i][j], 0.f);

    float4 ra[4], rb[4];
#pragma unroll
    for (int v = 0; v < 4; v++) {
        int linear = v * 256 + tid;
        int row = linear >> 3;
        int kq = (linear & 7) << 2;
        ra[v] = *(const float4*)(A + (size_t)(bm + row) * K + kq);
        rb[v] = *(const float4*)(Bw + (size_t)(bn + row) * K + kq);
    }

    for (int k0 = 0; k0 < K; k0 += 32) {
        // Store prefetched tile to smem with fp16 conversion
#pragma unroll
        for (int v = 0; v < 4; v++) {
            int linear = v * 256 + tid;
            int row = linear >> 3;
            int kq = (linear & 7) << 2;
            __half2* ap = (__half2*)&As[row * ALD + kq];
            ap[0] = __floats2half2_rn(ra[v].x, ra[v].y);
            ap[1] = __floats2half2_rn(ra[v].z, ra[v].w);
            __half2* bp = (__half2*)&Bs[row * ALD + kq];
            bp[0] = __floats2half2_rn(rb[v].x, rb[v].y);
            bp[1] = __floats2half2_rn(rb[v].z, rb[v].w);
        }
        __syncthreads();

        // Prefetch next tile (overlaps with mma below)
        if (k0 + 32 < K) {
#pragma unroll
            for (int v = 0; v < 4; v++) {
                int linear = v * 256 + tid;
                int row = linear >> 3;
                int kq = (linear & 7) << 2;
                ra[v] = *(const float4*)(A + (size_t)(bm + row) * K + k0 + 32 + kq);
                rb[v] = *(const float4*)(Bw + (size_t)(bn + row) * K + k0 + 32 + kq);
            }
        }

#pragma unroll
        for (int kk = 0; kk < 32; kk += 16) {
            wmma::fragment<wmma::matrix_a, 16, 16, 16, __half, wmma::row_major> af[2];
            wmma::fragment<wmma::matrix_b, 16, 16, 16, __half, wmma::col_major> bf[4];
#pragma unroll
            for (int i = 0; i < 2; i++)
                wmma::load_matrix_sync(af[i], &As[(warpM * 32 + i * 16) * ALD + kk], ALD);
#pragma unroll
            for (int j = 0; j < 4; j++)
                wmma::load_matrix_sync(bf[j], &Bs[(warpN * 64 + j * 16) * ALD + kk], ALD);
#pragma unroll
            for (int i = 0; i < 2; i++)
#pragma unroll
                for (int j = 0; j < 4; j++)
                    wmma::mma_sync(acc[i][j], af[i], bf[j], acc[i][j]);
        }
        __syncthreads();
    }

#pragma unroll
    for (int i = 0; i < 2; i++)
#pragma unroll
        for (int j = 0; j < 4; j++) {
            float* cp = C + (size_t)(bm + warpM * 32 + i * 16) * N + bn + warpN * 64 + j * 16;
            wmma::store_matrix_sync(cp, acc[i][j], N, wmma::mem_row_major);
        }
}

// ---------------------------------------------------------------------------
// Persistent LSTM layer, fp16 recurrent matmul (fp32 accumulate/state).
// 64 blocks x 256 threads; block owns 16 hidden units -> 64 gate rows.
// Whh slice fp16 resident in SMEM (129KB). h exchanged through global fp16.
// Warp w: Mt=w>>1 picks 16 gate rows, Nt=w&1 picks 16 batches; full K=1024
// in-warp (no cross-warp reduction). 4 k-striped accumulators.
// Epilogue: thread handles (unit u, batches bb and bb+16).
// ---------------------------------------------------------------------------
#define WLD2 1032   // halves, pad (mult of 8)
#define HLD2 1032
#define GLD2 36
#define REC_SMEM_BYTES ((64 * WLD2 + 32 * HLD2) * 2 + 64 * GLD2 * 4)

__device__ __forceinline__ float sigmoidf_(float x) {
    return 1.0f / (1.0f + __expf(-x));
}

__global__ void __launch_bounds__(256, 1)
lstm_layer_kernel(const float* __restrict__ xw,     // (S,B,4H)
                  const float* __restrict__ Whh,    // (4H,H)
                  const float* __restrict__ bih,
                  const float* __restrict__ bhh,
                  const float* __restrict__ res,    // (S,B,H) or null
                  const float* __restrict__ maskp,  // (S,B,H) or null
                  float* __restrict__ out,          // (S,B,H)
                  float* __restrict__ outm,         // (S,B,H) or null
                  __half* __restrict__ h0,
                  __half* __restrict__ h1)
{
    extern __shared__ __half smh[];
    __half* Wsh = smh;                          // [64][WLD2]
    __half* Hs  = smh + 64 * WLD2;              // [32][HLD2]
    float*  Gs  = (float*)(smh + 64 * WLD2 + 32 * HLD2);  // [64][GLD2]

    const int tid = threadIdx.x;
    const int jbase = blockIdx.x * 16;
    const int warp = tid >> 5;
    const int Mt = warp >> 1;     // 0..3
    const int Nt = warp & 1;      // 0..1

    // Load Whh slice -> fp16 smem. Local row r = g*16+u -> global g*HID+jbase+u
    for (int idx = tid; idx < 64 * 256; idx += 256) {
        int r = idx >> 8;                  // 0..63
        int kq = (idx & 255) << 2;         // 0..1020
        int grow = (r >> 4) * HID + jbase + (r & 15);
        float4 v = *(const float4*)(Whh + (size_t)grow * HID + kq);
        __half2* wp = (__half2*)&Wsh[r * WLD2 + kq];
        wp[0] = __floats2half2_rn(v.x, v.y);
        wp[1] = __floats2half2_rn(v.z, v.w);
    }

    // Zero initial h (h0, read at t=0): 32768 halves over 64 blocks
    {
        __half* z = h0 + blockIdx.x * 512;
        z[tid] = __float2half(0.f);
        z[tid + 256] = __float2half(0.f);
    }

    // Thread owns (unit u, batches bb, bb+16)
    const int u = tid & 15;
    const int bb = tid >> 4;      // 0..15
    const int j = jbase + u;
    float bias_[4];
#pragma unroll
    for (int g = 0; g < 4; g++)
        bias_[g] = bih[g * HID + j] + bhh[g * HID + j];
    float cc0 = 0.f, cc1 = 0.f;

    // Prefetch step-0 xw / res / mask for both batches
    float xwc[4][2], resc[2] = {0.f, 0.f}, maskc[2] = {1.f, 1.f};
#pragma unroll
    for (int p = 0; p < 2; p++) {
        int b = bb + p * 16;
        const float* xwt = xw + (size_t)b * G4;
#pragma unroll
        for (int g = 0; g < 4; g++) xwc[g][p] = xwt[g * HID + j];
        if (res)   resc[p]  = res[(size_t)b * HID + j];
        if (maskp) maskc[p] = maskp[(size_t)b * HID + j];
    }

    grid_sync_();

    for (int t = 0; t < S_LEN; t++) {
        const __half* hin  = (t & 1) ? h1 : h0;
        __half*       hout = (t & 1) ? h0 : h1;

        // Stage full h (32x1024 fp16 = 64KB): 4096 uint4, 16 per thread
        {
            const uint4* hsrc = (const uint4*)hin;
#pragma unroll
            for (int v = 0; v < 16; v++) {
                int i = v * 256 + tid;
                int b = i >> 7;              // 128 uint4 per batch row
                int kq = (i & 127) << 3;     // half index
                *(uint4*)&Hs[b * HLD2 + kq] = hsrc[i];
            }
        }

        // Prefetch next step's xw / res / mask (independent of h)
        float xwn[4][2] = {{0.f,0.f},{0.f,0.f},{0.f,0.f},{0.f,0.f}};
        float resn[2] = {0.f, 0.f}, maskn[2] = {1.f, 1.f};
        if (t + 1 < S_LEN) {
#pragma unroll
            for (int p = 0; p < 2; p++) {
                int b = bb + p * 16;
                const float* xwt = xw + ((size_t)(t + 1) * BSZ + b) * G4;
#pragma unroll
                for (int g = 0; g < 4; g++) xwn[g][p] = xwt[g * HID + j];
                if (res)   resn[p]  = res[((size_t)(t + 1) * BSZ + b) * HID + j];
                if (maskp) maskn[p] = maskp[((size_t)(t + 1) * BSZ + b) * HID + j];
            }
        }
        __syncthreads();

        // Recurrent matmul: warp computes 16 gate rows x 16 batches, K=1024.
        wmma::fragment<wmma::accumulator, 16, 16, 16, float> a0, a1, a2, a3;
        wmma::fill_fragment(a0, 0.f);
        wmma::fill_fragment(a1, 0.f);
        wmma::fill_fragment(a2, 0.f);
        wmma::fill_fragment(a3, 0.f);

        const __half* Wrow = &Wsh[(Mt * 16) * WLD2];
        const __half* Hrow = &Hs[(Nt * 16) * HLD2];
#pragma unroll
        for (int k = 0; k < 1024; k += 64) {
            wmma::fragment<wmma::matrix_a, 16, 16, 16, __half, wmma::row_major> af;
            wmma::fragment<wmma::matrix_b, 16, 16, 16, __half, wmma::col_major> bf;
            wmma::load_matrix_sync(af, Wrow + k, WLD2);
            wmma::load_matrix_sync(bf, Hrow + k, HLD2);
            wmma::mma_sync(a0, af, bf, a0);
            wmma::load_matrix_sync(af, Wrow + k + 16, WLD2);
            wmma::load_matrix_sync(bf, Hrow + k + 16, HLD2);
            wmma::mma_sync(a1, af, bf, a1);
            wmma::load_matrix_sync(af, Wrow + k + 32, WLD2);
            wmma::load_matrix_sync(bf, Hrow + k + 32, HLD2);
            wmma::mma_sync(a2, af, bf, a2);
            wmma::load_matrix_sync(af, Wrow + k + 48, WLD2);
            wmma::load_matrix_sync(bf, Hrow + k + 48, HLD2);
            wmma::mma_sync(a3, af, bf, a3);
        }
#pragma unroll
        for (int e = 0; e < a0.num_elements; e++)
            a0.x[e] += a1.x[e] + a2.x[e] + a3.x[e];

        wmma::store_matrix_sync(&Gs[(Mt * 16) * GLD2 + Nt * 16], a0, GLD2,
                                wmma::mem_row_major);
        __syncthreads();

        // Cell update for both owned batches
#pragma unroll
        for (int p = 0; p < 2; p++) {
            int b = bb + p * 16;
            float gi = Gs[(0 * 16 + u) * GLD2 + b] + xwc[0][p] + bias_[0];
            float gf = Gs[(1 * 16 + u) * GLD2 + b] + xwc[1][p] + bias_[1];
            float gg = Gs[(2 * 16 + u) * GLD2 + b] + xwc[2][p] + bias_[2];
            float go = Gs[(3 * 16 + u) * GLD2 + b] + xwc[3][p] + bias_[3];

            float ii = sigmoidf_(gi);
            float ff = sigmoidf_(gf);
            float oo = sigmoidf_(go);
            float gt = tanhf(gg);

            float& cc = p ? cc1 : cc0;
            cc = ff * cc + ii * gt;
            float hn = oo * tanhf(cc);

            hout[(size_t)b * HID + j] = __float2half_rn(hn);
            float ov = hn + resc[p];
            size_t ooff = ((size_t)t * BSZ + b) * HID + j;
            out[ooff] = ov;
            if (outm) outm[ooff] = ov * maskc[p];

#pragma unroll
            for (int g = 0; g < 4; g++) xwc[g][p] = xwn[g][p];
            resc[p] = resn[p];
            maskc[p] = maskn[p];
        }

        grid_sync_();
    }
}

// ---------------------------------------------------------------------------
// Host launcher
// ---------------------------------------------------------------------------
static void run_layer(const float* A, int K,
                      const float* Wih, const float* Whh,
                      const float* bih, const float* bhh,
                      const float* res_base, const float* maskp,
                      float* out_base, float* outm,
                      float* xw, __half* h0, __half* h1) {
    dim3 ggrid(G4 / 128, (S_LEN * BSZ) / 128);
    gemm_fp16_kernel<<<ggrid, 256>>>(A, Wih, xw, S_LEN * BSZ, G4, K);

    lstm_layer_kernel<<<NBLK_REC, 256, REC_SMEM_BYTES>>>(
        xw, Whh, bih, bhh, res_base, maskp, out_base, outm, h0, h1);
}

extern "C" void kernel_launch(void* const* d_in, const int* in_sizes, int n_in,
                              void* d_out, int out_size) {
    const float* input = (const float*)d_in[0];
    const float* Wih2 = (const float*)d_in[1];
    const float* Whh2 = (const float*)d_in[2];
    const float* bih2 = (const float*)d_in[3];
    const float* bhh2 = (const float*)d_in[4];
    const float* Wih3 = (const float*)d_in[5];
    const float* Whh3 = (const float*)d_in[6];
    const float* bih3 = (const float*)d_in[7];
    const float* bhh3 = (const float*)d_in[8];
    const float* Wih4 = (const float*)d_in[9];
    const float* Whh4 = (const float*)d_in[10];
    const float* bih4 = (const float*)d_in[11];
    const float* bhh4 = (const float*)d_in[12];
    const float* mask2 = (const float*)d_in[13];
    const float* mask3 = (const float*)d_in[14];
    float* out = (float*)d_out;

    float *xw, *out2, *out2m, *out3, *out3m;
    __half *h0, *h1;
    cudaGetSymbolAddress((void**)&xw, g_xw);
    cudaGetSymbolAddress((void**)&out2, g_out2);
    cudaGetSymbolAddress((void**)&out2m, g_out2m);
    cudaGetSymbolAddress((void**)&out3, g_out3);
    cudaGetSymbolAddress((void**)&out3m, g_out3m);
    cudaGetSymbolAddress((void**)&h0, g_h0);
    cudaGetSymbolAddress((void**)&h1, g_h1);

    cudaFuncSetAttribute(lstm_layer_kernel,
                         cudaFuncAttributeMaxDynamicSharedMemorySize,
                         REC_SMEM_BYTES);

    header_kernel<<<(BSZ * HID + 255) / 256, 256>>>(out);
    copy_src_kernel<<<(T_LEN * BSZ * (HID / 4) + 255) / 256, 256>>>(input, out);

    // Layer 2: input slice, K=DIN; no residual; writes out2 and out2*mask2
    run_layer(input + (size_t)BSZ * DIN, DIN,
              Wih2, Whh2, bih2, bhh2,
              nullptr, mask2, out2, out2m,
              xw, h0, h1);

    // Layer 3: in = out2m; residual out2; writes out3 and out3*mask3
    run_layer(out2m, HID,
              Wih3, Whh3, bih3, bhh3,
              out2, mask3, out3, out3m,
              xw, h0, h1);

    // Layer 4: in = out3m; residual out3 -> rows [1, 1+S) of output
    run_layer(out3m, HID,
              Wih4, Whh4, bih4, bhh4,
              out3, nullptr, out + (size_t)BSZ * HID, nullptr,
              xw, h0, h1);
}

// round 7
// speedup vs baseline: 6.2289x; 1.1546x over previous
#include <cuda_runtime.h>
#include <cuda_fp16.h>
#include <mma.h>
#include <cstddef>

using namespace nvcuda;

// Problem constants
#define S_LEN 256
#define T_LEN 256
#define BSZ   32
#define DIN   2048
#define HID   1024
#define G4    4096   // 4*HID

#define NBLK_REC 64    // recurrence blocks (barrier participants)
#define NBLK_GEMM 64   // embedded projection blocks

// Scratch (device globals; allocation-free rule)
__device__ float g_xw[(size_t)S_LEN * BSZ * G4];     // proj buffer A (128 MiB)
__device__ float g_xw2[(size_t)S_LEN * BSZ * G4];    // proj buffer B (128 MiB)
__device__ float g_out2[(size_t)S_LEN * BSZ * HID];  // layer2 out (residual for L3)
__device__ float g_out3[(size_t)S_LEN * BSZ * HID];  // layer3 out (residual for L4)
__device__ __half g_outh[(size_t)S_LEN * BSZ * HID]; // masked out, fp16 (GEMM A)
__device__ __half g_h0[BSZ * HID];
__device__ __half g_h1[BSZ * HID];

// Sync state
__device__ unsigned g_bar_count;
__device__ unsigned g_bar_gen;
__device__ unsigned g_progress;    // completed timesteps of current layer epoch

// Stream-ordered epoch reset: runs before each fused kernel, so embedded GEMM
// blocks can never observe a stale progress value from a previous layer or a
// previous graph replay. (This was the R6 post-timing divergence.)
__global__ void reset_sync_kernel() {
    g_progress = 0u;
    g_bar_count = 0u;
    __threadfence();
}

// Grid barrier among the 64 rec blocks; releaser publishes `prog`.
__device__ __forceinline__ void grid_sync_(unsigned prog) {
    __threadfence();   // order this thread's global writes before arrival
    __syncthreads();
    if (threadIdx.x == 0) {
        unsigned snap = *((volatile unsigned*)&g_bar_gen);
        unsigned old = atomicAdd(&g_bar_count, 1u);
        if (old == NBLK_REC - 1) {
            *((volatile unsigned*)&g_bar_count) = 0u;
            __threadfence();
            atomicExch(&g_progress, prog);
            atomicAdd(&g_bar_gen, 1u);
        } else {
            while (*((volatile unsigned*)&g_bar_gen) == snap) { }
        }
        __threadfence();
    }
    __syncthreads();
}

// ---------------------------------------------------------------------------
// Header row
// ---------------------------------------------------------------------------
__global__ void header_kernel(float* __restrict__ out) {
    int i = blockIdx.x * blockDim.x + threadIdx.x;
    if (i < BSZ * HID) {
        float v = 0.f;
        if (i == 0) v = (float)(1 + S_LEN + T_LEN);
        else if (i == 1) v = (float)(S_LEN + 1);
        else if (i == 2) v = (float)(S_LEN + 2);
        else if (i == 3) v = (float)(T_LEN + S_LEN + 1);
        out[i] = v;
    }
}

// ---------------------------------------------------------------------------
// src_tgt copy
// ---------------------------------------------------------------------------
__global__ void copy_src_kernel(const float* __restrict__ in, float* __restrict__ out) {
    int l = blockIdx.x * blockDim.x + threadIdx.x;
    const int TOT = T_LEN * BSZ * (HID / 4);
    if (l < TOT) {
        int j4 = l % (HID / 4);
        int rb = l / (HID / 4);
        int b  = rb % BSZ;
        int i  = rb / BSZ;
        size_t in_off  = ((size_t)(1 + S_LEN + i) * BSZ + b) * DIN + (size_t)j4 * 4;
        size_t out_off = ((size_t)(1 + S_LEN + i) * BSZ + b) * HID + (size_t)j4 * 4;
        float4 v = *(const float4*)(in + in_off);
        *(float4*)(out + out_off) = v;
    }
}

// ---------------------------------------------------------------------------
// FP16 GEMM-NT (fp32 accumulate) for the layer-2 projection (standalone).
// C[m,n] = sum_k A[m,k] * Bw[n,k]. BM=BN=128, BK=32.
// ---------------------------------------------------------------------------
#define ALD 40  // halves
__global__ void __launch_bounds__(256)
gemm_fp16_kernel(const float* __restrict__ A, const float* __restrict__ Bw,
                 float* __restrict__ C, int M, int N, int K) {
    __shared__ __half As[128 * ALD];
    __shared__ __half Bs[128 * ALD];

    int tid = threadIdx.x;
    int bm = blockIdx.y * 128;
    int bn = blockIdx.x * 128;
    int warp = tid >> 5;
    int warpM = warp & 3;
    int warpN = warp >> 2;

    wmma::fragment<wmma::accumulator, 16, 16, 16, float> acc[2][4];
#pragma unroll
    for (int i = 0; i < 2; i++)
#pragma unroll
        for (int j = 0; j < 4; j++) wmma::fill_fragment(acc[i][j], 0.f);

    float4 ra[4], rb[4];
#pragma unroll
    for (int v = 0; v < 4; v++) {
        int linear = v * 256 + tid;
        int row = linear >> 3;
        int kq = (linear & 7) << 2;
        ra[v] = *(const float4*)(A + (size_t)(bm + row) * K + kq);
        rb[v] = *(const float4*)(Bw + (size_t)(bn + row) * K + kq);
    }

    for (int k0 = 0; k0 < K; k0 += 32) {
#pragma unroll
        for (int v = 0; v < 4; v++) {
            int linear = v * 256 + tid;
            int row = linear >> 3;
            int kq = (linear & 7) << 2;
            __half2* ap = (__half2*)&As[row * ALD + kq];
            ap[0] = __floats2half2_rn(ra[v].x, ra[v].y);
            ap[1] = __floats2half2_rn(ra[v].z, ra[v].w);
            __half2* bp = (__half2*)&Bs[row * ALD + kq];
            bp[0] = __floats2half2_rn(rb[v].x, rb[v].y);
            bp[1] = __floats2half2_rn(rb[v].z, rb[v].w);
        }
        __syncthreads();

        if (k0 + 32 < K) {
#pragma unroll
            for (int v = 0; v < 4; v++) {
                int linear = v * 256 + tid;
                int row = linear >> 3;
                int kq = (linear & 7) << 2;
                ra[v] = *(const float4*)(A + (size_t)(bm + row) * K + k0 + 32 + kq);
                rb[v] = *(const float4*)(Bw + (size_t)(bn + row) * K + k0 + 32 + kq);
            }
        }

#pragma unroll
        for (int kk = 0; kk < 32; kk += 16) {
            wmma::fragment<wmma::matrix_a, 16, 16, 16, __half, wmma::row_major> af[2];
            wmma::fragment<wmma::matrix_b, 16, 16, 16, __half, wmma::col_major> bf[4];
#pragma unroll
            for (int i = 0; i < 2; i++)
                wmma::load_matrix_sync(af[i], &As[(warpM * 32 + i * 16) * ALD + kk], ALD);
#pragma unroll
            for (int j = 0; j < 4; j++)
                wmma::load_matrix_sync(bf[j], &Bs[(warpN * 64 + j * 16) * ALD + kk], ALD);
#pragma unroll
            for (int i = 0; i < 2; i++)
#pragma unroll
                for (int j = 0; j < 4; j++)
                    wmma::mma_sync(acc[i][j], af[i], bf[j], acc[i][j]);
        }
        __syncthreads();
    }

#pragma unroll
    for (int i = 0; i < 2; i++)
#pragma unroll
        for (int j = 0; j < 4; j++) {
            float* cp = C + (size_t)(bm + warpM * 32 + i * 16) * N + bn + warpN * 64 + j * 16;
            wmma::store_matrix_sync(cp, acc[i][j], N, wmma::mem_row_major);
        }
}

// ---------------------------------------------------------------------------
// Fused layer kernel: blocks 0..63 = persistent LSTM recurrence;
// blocks 64..127 = embedded next-layer projection GEMM consuming the masked
// fp16 output behind a progress watermark. Kernel completion (stream order)
// joins both roles; no in-kernel completion handshake needed.
// ---------------------------------------------------------------------------
#define WLD2 1032
#define HLD2 1032
#define GLD2 36
// rec smem: W(64x1032 h) + H(32x1032 h) + Gs(2x64x36 f)
#define SMEM_FUSED ((64 * WLD2 + 32 * HLD2) * 2 + 2 * 64 * GLD2 * 4)
// gemm smem: Bs(64x1032 h)=132096 + As(128x72 h)=18432 -> 150528 <= SMEM_FUSED
#define AGLD 72

__device__ __forceinline__ float sigmoidf_(float x) {
    return 1.0f / (1.0f + __expf(-x));
}

__global__ void __launch_bounds__(256, 1)
lstm_fused_kernel(const float* __restrict__ xw,     // (S,B,4H) this layer's proj
                  const float* __restrict__ Whh,    // (4H,H)
                  const float* __restrict__ bih,
                  const float* __restrict__ bhh,
                  const float* __restrict__ res,    // (S,B,H) or null
                  const float* __restrict__ maskp,  // (S,B,H) or null
                  float* __restrict__ out,          // (S,B,H)
                  __half* __restrict__ outm_h,      // (S,B,H) fp16 masked, or null
                  __half* __restrict__ h0,
                  __half* __restrict__ h1,
                  const float* __restrict__ WihN,   // (4H,H) next layer's Wih, or null
                  float* __restrict__ xw_next)      // (S,B,4H) next proj, or null
{
    extern __shared__ char smraw[];
    const int tid = threadIdx.x;
    const int warp = tid >> 5;

    if (blockIdx.x < NBLK_REC) {
        // ================= RECURRENCE ROLE =================
        __half* Wsh = (__half*)smraw;                          // [64][WLD2]
        __half* Hs  = (__half*)(smraw + 64 * WLD2 * 2);        // [32][HLD2]
        float*  Gs  = (float*)(smraw + (64 * WLD2 + 32 * HLD2) * 2); // [2][64][GLD2]

        const int jbase = blockIdx.x * 16;
        const int Mt = warp & 1;          // 32-gate-row group
        const int Nt = (warp >> 1) & 1;   // 16-batch group
        const int Ks = warp >> 2;         // K half (0/1)

        // Load Whh slice -> fp16 smem. Local row r=g*16+u -> global g*HID+jbase+u
        for (int idx = tid; idx < 64 * 256; idx += 256) {
            int r = idx >> 8;
            int kq = (idx & 255) << 2;
            int grow = (r >> 4) * HID + jbase + (r & 15);
            float4 v = *(const float4*)(Whh + (size_t)grow * HID + kq);
            __half2* wp = (__half2*)&Wsh[r * WLD2 + kq];
            wp[0] = __floats2half2_rn(v.x, v.y);
            wp[1] = __floats2half2_rn(v.z, v.w);
        }

        // Zero initial h
        {
            __half* z = h0 + blockIdx.x * 512;
            z[tid] = __float2half(0.f);
            z[tid + 256] = __float2half(0.f);
        }

        const int u = tid & 15;
        const int bb = tid >> 4;
        const int j = jbase + u;
        float bias_[4];
#pragma unroll
        for (int g = 0; g < 4; g++)
            bias_[g] = bih[g * HID + j] + bhh[g * HID + j];
        float cc0 = 0.f, cc1 = 0.f;

        float xwc[4][2], resc[2] = {0.f, 0.f}, maskc[2] = {1.f, 1.f};
#pragma unroll
        for (int p = 0; p < 2; p++) {
            int b = bb + p * 16;
            const float* xwt = xw + (size_t)b * G4;
#pragma unroll
            for (int g = 0; g < 4; g++) xwc[g][p] = xwt[g * HID + j];
            if (res)   resc[p]  = res[(size_t)b * HID + j];
            if (maskp) maskc[p] = maskp[(size_t)b * HID + j];
        }

        grid_sync_(0u);

        for (int t = 0; t < S_LEN; t++) {
            const __half* hin  = (t & 1) ? h1 : h0;
            __half*       hout = (t & 1) ? h0 : h1;

            // Stage full h (32x1024 fp16): 4096 uint4
            {
                const uint4* hsrc = (const uint4*)hin;
#pragma unroll
                for (int v = 0; v < 16; v++) {
                    int i = v * 256 + tid;
                    int b = i >> 7;
                    int kq = (i & 127) << 3;
                    *(uint4*)&Hs[b * HLD2 + kq] = hsrc[i];
                }
            }

            // Prefetch next step's xw / res / mask
            float xwn[4][2] = {{0.f,0.f},{0.f,0.f},{0.f,0.f},{0.f,0.f}};
            float resn[2] = {0.f, 0.f}, maskn[2] = {1.f, 1.f};
            if (t + 1 < S_LEN) {
#pragma unroll
                for (int p = 0; p < 2; p++) {
                    int b = bb + p * 16;
                    const float* xwt = xw + ((size_t)(t + 1) * BSZ + b) * G4;
#pragma unroll
                    for (int g = 0; g < 4; g++) xwn[g][p] = xwt[g * HID + j];
                    if (res)   resn[p]  = res[((size_t)(t + 1) * BSZ + b) * HID + j];
                    if (maskp) maskn[p] = maskp[((size_t)(t + 1) * BSZ + b) * HID + j];
                }
            }
            __syncthreads();

            // Warp: 32 gate rows x 16 batches, K half = 512
            wmma::fragment<wmma::accumulator, 16, 16, 16, float> f0, f1;
            wmma::fill_fragment(f0, 0.f);
            wmma::fill_fragment(f1, 0.f);

            const __half* Wr0 = Wsh + (Mt * 32) * WLD2;
            const __half* Wr1 = Wsh + (Mt * 32 + 16) * WLD2;
            const __half* Hr  = Hs + (Nt * 16) * HLD2;
            const int kbase = Ks * 512;
#pragma unroll
            for (int k = 0; k < 512; k += 32) {
                wmma::fragment<wmma::matrix_a, 16, 16, 16, __half, wmma::row_major> a0, a1, a2, a3;
                wmma::fragment<wmma::matrix_b, 16, 16, 16, __half, wmma::col_major> b0, b1;
                int kk = kbase + k;
                wmma::load_matrix_sync(b0, Hr + kk, HLD2);
                wmma::load_matrix_sync(a0, Wr0 + kk, WLD2);
                wmma::load_matrix_sync(a1, Wr1 + kk, WLD2);
                wmma::load_matrix_sync(b1, Hr + kk + 16, HLD2);
                wmma::load_matrix_sync(a2, Wr0 + kk + 16, WLD2);
                wmma::load_matrix_sync(a3, Wr1 + kk + 16, WLD2);
                wmma::mma_sync(f0, a0, b0, f0);
                wmma::mma_sync(f1, a1, b0, f1);
                wmma::mma_sync(f0, a2, b1, f0);
                wmma::mma_sync(f1, a3, b1, f1);
            }

            wmma::store_matrix_sync(&Gs[(size_t)Ks * 64 * GLD2 + (Mt * 32) * GLD2 + Nt * 16],
                                    f0, GLD2, wmma::mem_row_major);
            wmma::store_matrix_sync(&Gs[(size_t)Ks * 64 * GLD2 + (Mt * 32 + 16) * GLD2 + Nt * 16],
                                    f1, GLD2, wmma::mem_row_major);
            __syncthreads();

            // Cell update for both owned batches
#pragma unroll
            for (int p = 0; p < 2; p++) {
                int b = bb + p * 16;
                float gi = Gs[(0 * 16 + u) * GLD2 + b] + Gs[64 * GLD2 + (0 * 16 + u) * GLD2 + b] + xwc[0][p] + bias_[0];
                float gf = Gs[(1 * 16 + u) * GLD2 + b] + Gs[64 * GLD2 + (1 * 16 + u) * GLD2 + b] + xwc[1][p] + bias_[1];
                float gg = Gs[(2 * 16 + u) * GLD2 + b] + Gs[64 * GLD2 + (2 * 16 + u) * GLD2 + b] + xwc[2][p] + bias_[2];
                float go = Gs[(3 * 16 + u) * GLD2 + b] + Gs[64 * GLD2 + (3 * 16 + u) * GLD2 + b] + xwc[3][p] + bias_[3];

                float ii = sigmoidf_(gi);
                float ff = sigmoidf_(gf);
                float oo = sigmoidf_(go);
                float gt = tanhf(gg);

                float& cc = p ? cc1 : cc0;
                cc = ff * cc + ii * gt;
                float hn = oo * tanhf(cc);

                hout[(size_t)b * HID + j] = __float2half_rn(hn);
                float ov = hn + resc[p];
                size_t ooff = ((size_t)t * BSZ + b) * HID + j;
                out[ooff] = ov;
                if (outm_h) outm_h[ooff] = __float2half_rn(ov * maskc[p]);

#pragma unroll
                for (int g = 0; g < 4; g++) xwc[g][p] = xwn[g][p];
                resc[p] = resn[p];
                maskc[p] = maskn[p];
            }

            grid_sync_(t + 1);
        }
    } else {
        // ================= EMBEDDED PROJECTION GEMM ROLE =================
        if (WihN == nullptr) return;
        __half* Bs = (__half*)smraw;                   // [64][WLD2] Wih strip
        __half* As = (__half*)(smraw + 64 * WLD2 * 2); // [128][AGLD]

        const int gblk = blockIdx.x - NBLK_REC;
        const int n0 = gblk * 64;
        const int Mw = warp & 3;
        const int Nw = warp >> 2;

        // Load Wih strip rows [n0, n0+64) fp32 -> fp16 smem
        for (int idx = tid; idx < 64 * 256; idx += 256) {
            int r = idx >> 8;
            int kq = (idx & 255) << 2;
            float4 v = *(const float4*)(WihN + (size_t)(n0 + r) * HID + kq);
            __half2* bp = (__half2*)&Bs[r * WLD2 + kq];
            bp[0] = __floats2half2_rn(v.x, v.y);
            bp[1] = __floats2half2_rn(v.z, v.w);
        }
        __syncthreads();

        for (int mt = 0; mt < 64; mt++) {
            // Wait until the 4 timesteps covering rows [mt*128, mt*128+128) are done
            if (tid == 0) {
                unsigned need = (unsigned)((mt + 1) * 4);
                while (*((volatile unsigned*)&g_progress) < need) { }
            }
            __syncthreads();

            const int m0 = mt * 128;
            wmma::fragment<wmma::accumulator, 16, 16, 16, float> acc[2][2];
#pragma unroll
            for (int i = 0; i < 2; i++)
#pragma unroll
                for (int jj = 0; jj < 2; jj++) wmma::fill_fragment(acc[i][jj], 0.f);

            for (int k0 = 0; k0 < HID; k0 += 64) {
                // Stage A chunk: 128 rows x 64 halves from masked fp16 output
#pragma unroll
                for (int v = 0; v < 4; v++) {
                    int idx = v * 256 + tid;
                    int row = idx >> 3;
                    int c8 = (idx & 7) << 3;
                    *(uint4*)&As[row * AGLD + c8] =
                        *(const uint4*)(outm_h + (size_t)(m0 + row) * HID + k0 + c8);
                }
                __syncthreads();

#pragma unroll
                for (int kk = 0; kk < 64; kk += 16) {
                    wmma::fragment<wmma::matrix_a, 16, 16, 16, __half, wmma::row_major> af[2];
                    wmma::fragment<wmma::matrix_b, 16, 16, 16, __half, wmma::col_major> bf[2];
#pragma unroll
                    for (int i = 0; i < 2; i++)
                        wmma::load_matrix_sync(af[i], &As[(Mw * 32 + i * 16) * AGLD + kk], AGLD);
#pragma unroll
                    for (int jj = 0; jj < 2; jj++)
                        wmma::load_matrix_sync(bf[jj], &Bs[(Nw * 32 + jj * 16) * WLD2 + k0 + kk], WLD2);
#pragma unroll
                    for (int i = 0; i < 2; i++)
#pragma unroll
                        for (int jj = 0; jj < 2; jj++)
                            wmma::mma_sync(acc[i][jj], af[i], bf[jj], acc[i][jj]);
                }
                __syncthreads();
            }

#pragma unroll
            for (int i = 0; i < 2; i++)
#pragma unroll
                for (int jj = 0; jj < 2; jj++) {
                    float* cp = xw_next + (size_t)(m0 + Mw * 32 + i * 16) * G4
                              + n0 + Nw * 32 + jj * 16;
                    wmma::store_matrix_sync(cp, acc[i][jj], G4, wmma::mem_row_major);
                }
        }
    }
}

// ---------------------------------------------------------------------------
// Host launcher
// ---------------------------------------------------------------------------
extern "C" void kernel_launch(void* const* d_in, const int* in_sizes, int n_in,
                              void* d_out, int out_size) {
    const float* input = (const float*)d_in[0];
    const float* Wih2 = (const float*)d_in[1];
    const float* Whh2 = (const float*)d_in[2];
    const float* bih2 = (const float*)d_in[3];
    const float* bhh2 = (const float*)d_in[4];
    const float* Wih3 = (const float*)d_in[5];
    const float* Whh3 = (const float*)d_in[6];
    const float* bih3 = (const float*)d_in[7];
    const float* bhh3 = (const float*)d_in[8];
    const float* Wih4 = (const float*)d_in[9];
    const float* Whh4 = (const float*)d_in[10];
    const float* bih4 = (const float*)d_in[11];
    const float* bhh4 = (const float*)d_in[12];
    const float* mask2 = (const float*)d_in[13];
    const float* mask3 = (const float*)d_in[14];
    float* out = (float*)d_out;

    float *xw, *xw2, *out2, *out3;
    __half *outh, *h0, *h1;
    cudaGetSymbolAddress((void**)&xw, g_xw);
    cudaGetSymbolAddress((void**)&xw2, g_xw2);
    cudaGetSymbolAddress((void**)&out2, g_out2);
    cudaGetSymbolAddress((void**)&out3, g_out3);
    cudaGetSymbolAddress((void**)&outh, g_outh);
    cudaGetSymbolAddress((void**)&h0, g_h0);
    cudaGetSymbolAddress((void**)&h1, g_h1);

    cudaFuncSetAttribute(lstm_fused_kernel,
                         cudaFuncAttributeMaxDynamicSharedMemorySize, SMEM_FUSED);

    header_kernel<<<(BSZ * HID + 255) / 256, 256>>>(out);
    copy_src_kernel<<<(T_LEN * BSZ * (HID / 4) + 255) / 256, 256>>>(input, out);

    // Layer-2 projection (standalone): xw = input[1:1+S] @ Wih2^T
    dim3 ggrid(G4 / 128, (S_LEN * BSZ) / 128);
    gemm_fp16_kernel<<<ggrid, 256>>>(input + (size_t)BSZ * DIN, Wih2, xw,
                                     S_LEN * BSZ, G4, DIN);

    // Layer 2: rec(xw) + embedded GEMM produces xw3 into g_xw2
    reset_sync_kernel<<<1, 1>>>();
    lstm_fused_kernel<<<NBLK_REC + NBLK_GEMM, 256, SMEM_FUSED>>>(
        xw, Whh2, bih2, bhh2,
        nullptr, mask2, out2, outh, h0, h1,
        Wih3, xw2);

    // Layer 3: rec(xw2) + embedded GEMM produces xw4 into g_xw
    reset_sync_kernel<<<1, 1>>>();
    lstm_fused_kernel<<<NBLK_REC + NBLK_GEMM, 256, SMEM_FUSED>>>(
        xw2, Whh3, bih3, bhh3,
        out2, mask3, out3, outh, h0, h1,
        Wih4, xw);

    // Layer 4: rec only -> rows [1, 1+S) of output
    reset_sync_kernel<<<1, 1>>>();
    lstm_fused_kernel<<<NBLK_REC, 256, SMEM_FUSED>>>(
        xw, Whh4, bih4, bhh4,
        out3, nullptr, out + (size_t)BSZ * HID, nullptr, h0, h1,
        nullptr, nullptr);
}

// round 9
// speedup vs baseline: 7.1317x; 1.1449x over previous
#include <cuda_runtime.h>
#include <cuda_fp16.h>
#include <mma.h>
#include <cstddef>

using namespace nvcuda;

// Problem constants
#define S_LEN 256
#define T_LEN 256
#define BSZ   32
#define DIN   2048
#define HID   1024
#define G4    4096   // 4*HID

#define NBLK_REC 64    // recurrence blocks (barrier participants)
#define NBLK_GEMM 64   // embedded projection blocks

// Scratch (device globals; allocation-free rule)
__device__ float g_xw[(size_t)S_LEN * BSZ * G4];     // proj buffer A (128 MiB)
__device__ float g_xw2[(size_t)S_LEN * BSZ * G4];    // proj buffer B (128 MiB)
__device__ float g_out2[(size_t)S_LEN * BSZ * HID];  // layer2 out (residual for L3)
__device__ float g_out3[(size_t)S_LEN * BSZ * HID];  // layer3 out (residual for L4)
__device__ __half g_outh[(size_t)S_LEN * BSZ * HID]; // masked out, fp16 (GEMM A)
__device__ __half g_h0[BSZ * HID];
__device__ __half g_h1[BSZ * HID];
__device__ __half g_ah[(size_t)S_LEN * BSZ * DIN];   // input slice fp16 (32 MiB)
__device__ __half g_wh[(size_t)G4 * DIN];            // Wih2 fp16 (16 MiB)

// Sync state
__device__ unsigned g_bar_count;
__device__ unsigned g_bar_gen;
__device__ unsigned g_progress;    // completed timesteps of current layer epoch

// Stream-ordered epoch reset before each fused kernel (replay-safe).
__global__ void reset_sync_kernel() {
    g_progress = 0u;
    g_bar_count = 0u;
    __threadfence();
}

// Grid barrier among the 64 rec blocks; releaser publishes `prog`.
// Fences only in tid0 (cumulativity via the preceding __syncthreads).
// Trailing fence also invalidates L1 (CCTL.IVALL) for fresh cross-SM reads.
__device__ __forceinline__ void grid_sync_(unsigned prog) {
    __syncthreads();
    if (threadIdx.x == 0) {
        __threadfence();   // block's prior writes -> device scope (cumulative)
        unsigned snap = *((volatile unsigned*)&g_bar_gen);
        unsigned old = atomicAdd(&g_bar_count, 1u);
        if (old == NBLK_REC - 1) {
            *((volatile unsigned*)&g_bar_count) = 0u;
            __threadfence();
            atomicExch(&g_progress, prog);
            atomicAdd(&g_bar_gen, 1u);
        } else {
            while (*((volatile unsigned*)&g_bar_gen) == snap) { }
        }
        __threadfence();
    }
    __syncthreads();
}

// ---------------------------------------------------------------------------
// Header row
// ---------------------------------------------------------------------------
__global__ void header_kernel(float* __restrict__ out) {
    int i = blockIdx.x * blockDim.x + threadIdx.x;
    if (i < BSZ * HID) {
        float v = 0.f;
        if (i == 0) v = (float)(1 + S_LEN + T_LEN);
        else if (i == 1) v = (float)(S_LEN + 1);
        else if (i == 2) v = (float)(S_LEN + 2);
        else if (i == 3) v = (float)(T_LEN + S_LEN + 1);
        out[i] = v;
    }
}

// ---------------------------------------------------------------------------
// src_tgt copy
// ---------------------------------------------------------------------------
__global__ void copy_src_kernel(const float* __restrict__ in, float* __restrict__ out) {
    int l = blockIdx.x * blockDim.x + threadIdx.x;
    const int TOT = T_LEN * BSZ * (HID / 4);
    if (l < TOT) {
        int j4 = l % (HID / 4);
        int rb = l / (HID / 4);
        int b  = rb % BSZ;
        int i  = rb / BSZ;
        size_t in_off  = ((size_t)(1 + S_LEN + i) * BSZ + b) * DIN + (size_t)j4 * 4;
        size_t out_off = ((size_t)(1 + S_LEN + i) * BSZ + b) * HID + (size_t)j4 * 4;
        float4 v = *(const float4*)(in + in_off);
        *(float4*)(out + out_off) = v;
    }
}

// ---------------------------------------------------------------------------
// fp32 -> fp16 bulk convert (n4 = count of float4)
// ---------------------------------------------------------------------------
__global__ void f2h_kernel(const float* __restrict__ src, __half* __restrict__ dst,
                           int n4) {
    int i = blockIdx.x * blockDim.x + threadIdx.x;
    if (i < n4) {
        float4 v = ((const float4*)src)[i];
        __half2* d = (__half2*)dst + 2 * (size_t)i;
        d[0] = __floats2half2_rn(v.x, v.y);
        d[1] = __floats2half2_rn(v.z, v.w);
    }
}

// ---------------------------------------------------------------------------
// FP16-in GEMM-NT (fp32 accumulate): C[m,n] = sum_k A[m,k] * Bw[n,k]
// A, Bw already fp16. BM=BN=128, BK=32, 256 threads, register prefetch.
// ---------------------------------------------------------------------------
#define ALD 40  // halves
__global__ void __launch_bounds__(256)
gemm_fp16h_kernel(const __half* __restrict__ A, const __half* __restrict__ Bw,
                  float* __restrict__ C, int M, int N, int K) {
    __shared__ __half As[128 * ALD];
    __shared__ __half Bs[128 * ALD];

    int tid = threadIdx.x;
    int bm = blockIdx.y * 128;
    int bn = blockIdx.x * 128;
    int warp = tid >> 5;
    int warpM = warp & 3;
    int warpN = warp >> 2;

    wmma::fragment<wmma::accumulator, 16, 16, 16, float> acc[2][4];
#pragma unroll
    for (int i = 0; i < 2; i++)
#pragma unroll
        for (int j = 0; j < 4; j++) wmma::fill_fragment(acc[i][j], 0.f);

    uint4 ra[2], rb[2];
#pragma unroll
    for (int v = 0; v < 2; v++) {
        int idx = v * 256 + tid;        // 0..511
        int row = idx >> 2;             // 0..127
        int c8 = (idx & 3) << 3;        // 0,8,16,24
        ra[v] = *(const uint4*)(A + (size_t)(bm + row) * K + c8);
        rb[v] = *(const uint4*)(Bw + (size_t)(bn + row) * K + c8);
    }

    for (int k0 = 0; k0 < K; k0 += 32) {
#pragma unroll
        for (int v = 0; v < 2; v++) {
            int idx = v * 256 + tid;
            int row = idx >> 2;
            int c8 = (idx & 3) << 3;
            *(uint4*)&As[row * ALD + c8] = ra[v];
            *(uint4*)&Bs[row * ALD + c8] = rb[v];
        }
        __syncthreads();

        if (k0 + 32 < K) {
#pragma unroll
            for (int v = 0; v < 2; v++) {
                int idx = v * 256 + tid;
                int row = idx >> 2;
                int c8 = (idx & 3) << 3;
                ra[v] = *(const uint4*)(A + (size_t)(bm + row) * K + k0 + 32 + c8);
                rb[v] = *(const uint4*)(Bw + (size_t)(bn + row) * K + k0 + 32 + c8);
            }
        }

#pragma unroll
        for (int kk = 0; kk < 32; kk += 16) {
            wmma::fragment<wmma::matrix_a, 16, 16, 16, __half, wmma::row_major> af[2];
            wmma::fragment<wmma::matrix_b, 16, 16, 16, __half, wmma::col_major> bf[4];
#pragma unroll
            for (int i = 0; i < 2; i++)
                wmma::load_matrix_sync(af[i], &As[(warpM * 32 + i * 16) * ALD + kk], ALD);
#pragma unroll
            for (int j = 0; j < 4; j++)
                wmma::load_matrix_sync(bf[j], &Bs[(warpN * 64 + j * 16) * ALD + kk], ALD);
#pragma unroll
            for (int i = 0; i < 2; i++)
#pragma unroll
                for (int j = 0; j < 4; j++)
                    wmma::mma_sync(acc[i][j], af[i], bf[j], acc[i][j]);
        }
        __syncthreads();
    }

#pragma unroll
    for (int i = 0; i < 2; i++)
#pragma unroll
        for (int j = 0; j < 4; j++) {
            float* cp = C + (size_t)(bm + warpM * 32 + i * 16) * N + bn + warpN * 64 + j * 16;
            wmma::store_matrix_sync(cp, acc[i][j], N, wmma::mem_row_major);
        }
}

// ---------------------------------------------------------------------------
// Fused layer kernel: blocks 0..63 = persistent LSTM recurrence (Whh
// fragments REGISTER-resident; SMEM aliased: Wsh at init, then Hs+Gs);
// blocks 64..127 = embedded next-layer projection GEMM behind a progress
// watermark.
// ---------------------------------------------------------------------------
#define WLD2 1032   // halves (ld, mult of 8)
#define HLD2 1032
#define GLD2 36     // floats (ld, mult of 4)
#define GSLAB (64 * GLD2)          // one K-partial slab: 64 rows x 36
// rec region: max(Wsh 64*1032*2 = 132096, Hs 32*1032*2 + Gs 4*64*36*4 = 102912)
// gemm region: Bs 64*1032*2 + As 128*72*2 = 150528
#define SMEM_FUSED (64 * WLD2 * 2 + 128 * 72 * 2)
#define AGLD 72

__device__ __forceinline__ float sigmoidf_(float x) {
    return 1.0f / (1.0f + __expf(-x));
}

__global__ void __launch_bounds__(256, 1)
lstm_fused_kernel(const float* __restrict__ xw,     // (S,B,4H) this layer's proj
                  const float* __restrict__ Whh,    // (4H,H)
                  const float* __restrict__ bih,
                  const float* __restrict__ bhh,
                  const float* __restrict__ res,    // (S,B,H) or null
                  const float* __restrict__ maskp,  // (S,B,H) or null
                  float* __restrict__ out,          // (S,B,H)
                  __half* __restrict__ outm_h,      // (S,B,H) fp16 masked, or null
                  __half* __restrict__ h0,
                  __half* __restrict__ h1,
                  const float* __restrict__ WihN,   // next layer's Wih, or null
                  float* __restrict__ xw_next)      // next proj, or null
{
    extern __shared__ char smraw[];
    const int tid = threadIdx.x;
    const int warp = tid >> 5;

    if (blockIdx.x < NBLK_REC) {
        // ================= RECURRENCE ROLE =================
        __half* Wsh = (__half*)smraw;                    // [64][WLD2]  (init only)
        __half* Hs  = (__half*)smraw;                    // [32][HLD2]  (aliases Wsh)
        float*  Gs  = (float*)(smraw + 32 * HLD2 * 2);   // [4][64][GLD2]

        const int jbase = blockIdx.x * 16;
        const int Mt = warp & 1;      // 32-row group (rows Mt*32..Mt*32+31)
        const int Ks = warp >> 1;     // K quarter (256 wide)

        // Load Whh slice -> fp16 smem. Local row r=g*16+u -> global g*HID+jbase+u
        for (int idx = tid; idx < 64 * 256; idx += 256) {
            int r = idx >> 8;
            int kq = (idx & 255) << 2;
            int grow = (r >> 4) * HID + jbase + (r & 15);
            float4 v = *(const float4*)(Whh + (size_t)grow * HID + kq);
            __half2* wp = (__half2*)&Wsh[r * WLD2 + kq];
            wp[0] = __floats2half2_rn(v.x, v.y);
            wp[1] = __floats2half2_rn(v.z, v.w);
        }
        __syncthreads();

        // Preload this warp's 32 Whh fragments into registers (persist all steps)
        wmma::fragment<wmma::matrix_a, 16, 16, 16, __half, wmma::row_major> afr[2][16];
#pragma unroll
        for (int m = 0; m < 2; m++)
#pragma unroll
            for (int kf = 0; kf < 16; kf++)
                wmma::load_matrix_sync(afr[m][kf],
                    &Wsh[(Mt * 32 + m * 16) * WLD2 + Ks * 256 + kf * 16], WLD2);
        __syncthreads();   // Wsh region now dead -> reused as Hs/Gs

        // Zero initial h
        {
            __half* z = h0 + blockIdx.x * 512;
            z[tid] = __float2half(0.f);
            z[tid + 256] = __float2half(0.f);
        }

        const int u = tid & 15;
        const int bb = tid >> 4;      // 0..15
        const int j = jbase + u;
        float bias_[4];
#pragma unroll
        for (int g = 0; g < 4; g++)
            bias_[g] = bih[g * HID + j] + bhh[g * HID + j];
        float cc0 = 0.f, cc1 = 0.f;

        float xwc[4][2], resc[2] = {0.f, 0.f}, maskc[2] = {1.f, 1.f};
#pragma unroll
        for (int p = 0; p < 2; p++) {
            int b = bb + p * 16;
            const float* xwt = xw + (size_t)b * G4;
#pragma unroll
            for (int g = 0; g < 4; g++) xwc[g][p] = xwt[g * HID + j];
            if (res)   resc[p]  = res[(size_t)b * HID + j];
            if (maskp) maskc[p] = maskp[(size_t)b * HID + j];
        }

        grid_sync_(0u);

        for (int t = 0; t < S_LEN; t++) {
            const __half* hin  = (t & 1) ? h1 : h0;
            __half*       hout = (t & 1) ? h0 : h1;

            // Stage full h (32x1024 fp16) via L2 (ldcg: no stale-L1 dependence)
            {
                const uint4* hsrc = (const uint4*)hin;
#pragma unroll
                for (int v = 0; v < 16; v++) {
                    int i = v * 256 + tid;
                    int b = i >> 7;
                    int kq = (i & 127) << 3;
                    uint4 x = __ldcg(hsrc + i);
                    *(uint4*)&Hs[b * HLD2 + kq] = x;
                }
            }

            // Prefetch next step's xw / res / mask
            float xwn[4][2] = {{0.f,0.f},{0.f,0.f},{0.f,0.f},{0.f,0.f}};
            float resn[2] = {0.f, 0.f}, maskn[2] = {1.f, 1.f};
            if (t + 1 < S_LEN) {
#pragma unroll
                for (int p = 0; p < 2; p++) {
                    int b = bb + p * 16;
                    const float* xwt = xw + ((size_t)(t + 1) * BSZ + b) * G4;
#pragma unroll
                    for (int g = 0; g < 4; g++) xwn[g][p] = xwt[g * HID + j];
                    if (res)   resn[p]  = res[((size_t)(t + 1) * BSZ + b) * HID + j];
                    if (maskp) maskn[p] = maskp[((size_t)(t + 1) * BSZ + b) * HID + j];
                }
            }
            __syncthreads();

            // Warp: 32 gate rows x 32 batches x 256 K. A from registers.
            wmma::fragment<wmma::accumulator, 16, 16, 16, float> acc[2][2];
#pragma unroll
            for (int m = 0; m < 2; m++)
#pragma unroll
                for (int n = 0; n < 2; n++) wmma::fill_fragment(acc[m][n], 0.f);

            const int kb = Ks * 256;
#pragma unroll
            for (int kf = 0; kf < 16; kf++) {
                wmma::fragment<wmma::matrix_b, 16, 16, 16, __half, wmma::col_major> b0, b1;
                wmma::load_matrix_sync(b0, Hs + kb + kf * 16, HLD2);
                wmma::load_matrix_sync(b1, Hs + 16 * HLD2 + kb + kf * 16, HLD2);
                wmma::mma_sync(acc[0][0], afr[0][kf], b0, acc[0][0]);
                wmma::mma_sync(acc[1][0], afr[1][kf], b0, acc[1][0]);
                wmma::mma_sync(acc[0][1], afr[0][kf], b1, acc[0][1]);
                wmma::mma_sync(acc[1][1], afr[1][kf], b1, acc[1][1]);
            }

#pragma unroll
            for (int m = 0; m < 2; m++)
#pragma unroll
                for (int n = 0; n < 2; n++)
                    wmma::store_matrix_sync(
                        &Gs[Ks * GSLAB + (Mt * 32 + m * 16) * GLD2 + n * 16],
                        acc[m][n], GLD2, wmma::mem_row_major);
            __syncthreads();

            // Cell update for both owned batches (sum 4 K-partial slabs)
#pragma unroll
            for (int p = 0; p < 2; p++) {
                int b = bb + p * 16;
                float gg4[4];
#pragma unroll
                for (int g = 0; g < 4; g++) {
                    float s = xwc[g][p] + bias_[g];
#pragma unroll
                    for (int sl = 0; sl < 4; sl++)
                        s += Gs[sl * GSLAB + (g * 16 + u) * GLD2 + b];
                    gg4[g] = s;
                }

                float ii = sigmoidf_(gg4[0]);
                float ff = sigmoidf_(gg4[1]);
                float gt = tanhf(gg4[2]);
                float oo = sigmoidf_(gg4[3]);

                float& cc = p ? cc1 : cc0;
                cc = ff * cc + ii * gt;
                float hn = oo * tanhf(cc);

                hout[(size_t)b * HID + j] = __float2half_rn(hn);
                float ov = hn + resc[p];
                size_t ooff = ((size_t)t * BSZ + b) * HID + j;
                out[ooff] = ov;
                if (outm_h) outm_h[ooff] = __float2half_rn(ov * maskc[p]);

#pragma unroll
                for (int g = 0; g < 4; g++) xwc[g][p] = xwn[g][p];
                resc[p] = resn[p];
                maskc[p] = maskn[p];
            }

            grid_sync_(t + 1);
        }
    } else {
        // ================= EMBEDDED PROJECTION GEMM ROLE =================
        if (WihN == nullptr) return;
        __half* Bs = (__half*)smraw;                   // [64][WLD2] Wih strip
        __half* As = (__half*)(smraw + 64 * WLD2 * 2); // [128][AGLD]

        const int gblk = blockIdx.x - NBLK_REC;
        const int n0 = gblk * 64;
        const int Mw = warp & 3;
        const int Nw = warp >> 2;

        // Load Wih strip rows [n0, n0+64) fp32 -> fp16 smem
        for (int idx = tid; idx < 64 * 256; idx += 256) {
            int r = idx >> 8;
            int kq = (idx & 255) << 2;
            float4 v = *(const float4*)(WihN + (size_t)(n0 + r) * HID + kq);
            __half2* bp = (__half2*)&Bs[r * WLD2 + kq];
            bp[0] = __floats2half2_rn(v.x, v.y);
            bp[1] = __floats2half2_rn(v.z, v.w);
        }
        __syncthreads();

        for (int mt = 0; mt < 64; mt++) {
            // Wait until the 4 timesteps covering rows [mt*128, mt*128+128) are done
            if (tid == 0) {
                unsigned need = (unsigned)((mt + 1) * 4);
                while (*((volatile unsigned*)&g_progress) < need) { }
            }
            __syncthreads();

            const int m0 = mt * 128;
            wmma::fragment<wmma::accumulator, 16, 16, 16, float> acc[2][2];
#pragma unroll
            for (int i = 0; i < 2; i++)
#pragma unroll
                for (int jj = 0; jj < 2; jj++) wmma::fill_fragment(acc[i][jj], 0.f);

            for (int k0 = 0; k0 < HID; k0 += 64) {
                // Stage A chunk: 128 rows x 64 halves from masked fp16 output
#pragma unroll
                for (int v = 0; v < 4; v++) {
                    int idx = v * 256 + tid;
                    int row = idx >> 3;
                    int c8 = (idx & 7) << 3;
                    *(uint4*)&As[row * AGLD + c8] =
                        __ldcg((const uint4*)(outm_h + (size_t)(m0 + row) * HID + k0 + c8));
                }
                __syncthreads();

#pragma unroll
                for (int kk = 0; kk < 64; kk += 16) {
                    wmma::fragment<wmma::matrix_a, 16, 16, 16, __half, wmma::row_major> af[2];
                    wmma::fragment<wmma::matrix_b, 16, 16, 16, __half, wmma::col_major> bf[2];
#pragma unroll
                    for (int i = 0; i < 2; i++)
                        wmma::load_matrix_sync(af[i], &As[(Mw * 32 + i * 16) * AGLD + kk], AGLD);
#pragma unroll
                    for (int jj = 0; jj < 2; jj++)
                        wmma::load_matrix_sync(bf[jj], &Bs[(Nw * 32 + jj * 16) * WLD2 + k0 + kk], WLD2);
#pragma unroll
                    for (int i = 0; i < 2; i++)
#pragma unroll
                        for (int jj = 0; jj < 2; jj++)
                            wmma::mma_sync(acc[i][jj], af[i], bf[jj], acc[i][jj]);
                }
                __syncthreads();
            }

#pragma unroll
            for (int i = 0; i < 2; i++)
#pragma unroll
                for (int jj = 0; jj < 2; jj++) {
                    float* cp = xw_next + (size_t)(m0 + Mw * 32 + i * 16) * G4
                              + n0 + Nw * 32 + jj * 16;
                    wmma::store_matrix_sync(cp, acc[i][jj], G4, wmma::mem_row_major);
                }
        }
    }
}

// ---------------------------------------------------------------------------
// Host launcher
// ---------------------------------------------------------------------------
extern "C" void kernel_launch(void* const* d_in, const int* in_sizes, int n_in,
                              void* d_out, int out_size) {
    const float* input = (const float*)d_in[0];
    const float* Wih2 = (const float*)d_in[1];
    const float* Whh2 = (const float*)d_in[2];
    const float* bih2 = (const float*)d_in[3];
    const float* bhh2 = (const float*)d_in[4];
    const float* Wih3 = (const float*)d_in[5];
    const float* Whh3 = (const float*)d_in[6];
    const float* bih3 = (const float*)d_in[7];
    const float* bhh3 = (const float*)d_in[8];
    const float* Wih4 = (const float*)d_in[9];
    const float* Whh4 = (const float*)d_in[10];
    const float* bih4 = (const float*)d_in[11];
    const float* bhh4 = (const float*)d_in[12];
    const float* mask2 = (const float*)d_in[13];
    const float* mask3 = (const float*)d_in[14];
    float* out = (float*)d_out;

    float *xw, *xw2, *out2, *out3;
    __half *outh, *h0, *h1, *ah, *wh;
    cudaGetSymbolAddress((void**)&xw, g_xw);
    cudaGetSymbolAddress((void**)&xw2, g_xw2);
    cudaGetSymbolAddress((void**)&out2, g_out2);
    cudaGetSymbolAddress((void**)&out3, g_out3);
    cudaGetSymbolAddress((void**)&outh, g_outh);
    cudaGetSymbolAddress((void**)&h0, g_h0);
    cudaGetSymbolAddress((void**)&h1, g_h1);
    cudaGetSymbolAddress((void**)&ah, g_ah);
    cudaGetSymbolAddress((void**)&wh, g_wh);

    cudaFuncSetAttribute(lstm_fused_kernel,
                         cudaFuncAttributeMaxDynamicSharedMemorySize, SMEM_FUSED);

    header_kernel<<<(BSZ * HID + 255) / 256, 256>>>(out);
    copy_src_kernel<<<(T_LEN * BSZ * (HID / 4) + 255) / 256, 256>>>(input, out);

    // Convert layer-2 GEMM operands to fp16
    {
        int nA4 = (S_LEN * BSZ * DIN) / 4;
        f2h_kernel<<<(nA4 + 255) / 256, 256>>>(input + (size_t)BSZ * DIN, ah, nA4);
        int nW4 = (G4 * DIN) / 4;
        f2h_kernel<<<(nW4 + 255) / 256, 256>>>(Wih2, wh, nW4);
    }

    // Layer-2 projection (standalone, fp16 operands): xw = ah @ wh^T
    dim3 ggrid(G4 / 128, (S_LEN * BSZ) / 128);
    gemm_fp16h_kernel<<<ggrid, 256>>>(ah, wh, xw, S_LEN * BSZ, G4, DIN);

    // Layer 2: rec(xw) + embedded GEMM produces xw3 into g_xw2
    reset_sync_kernel<<<1, 1>>>();
    lstm_fused_kernel<<<NBLK_REC + NBLK_GEMM, 256, SMEM_FUSED>>>(
        xw, Whh2, bih2, bhh2,
        nullptr, mask2, out2, outh, h0, h1,
        Wih3, xw2);

    // Layer 3: rec(xw2) + embedded GEMM produces xw4 into g_xw
    reset_sync_kernel<<<1, 1>>>();
    lstm_fused_kernel<<<NBLK_REC + NBLK_GEMM, 256, SMEM_FUSED>>>(
        xw2, Whh3, bih3, bhh3,
        out2, mask3, out3, outh, h0, h1,
        Wih4, xw);

    // Layer 4: rec only -> rows [1, 1+S) of output
    reset_sync_kernel<<<1, 1>>>();
    lstm_fused_kernel<<<NBLK_REC, 256, SMEM_FUSED>>>(
        xw, Whh4, bih4, bhh4,
        out3, nullptr, out + (size_t)BSZ * HID, nullptr, h0, h1,
        nullptr, nullptr);
}